// round 12
// baseline (speedup 1.0000x reference)
#include <cuda_runtime.h>
#include <cuda_fp16.h>
#include <stdint.h>

#define VV 3
#define NN 8192
#define HH 128
#define ADIM 64
#define FOUT 128
#define WORDS 256
#define SCALE1 256.0f
#define SCALE2 1024.0f
#define KSPLIT 6
#define NPART 64

static __device__ uint32_t g_packed[VV][NN][WORDS];              // word 4c+k, bit l <-> col 128c+4l+k
static __device__ float    g_dinv[VV][NN];                       // natural order
static __device__ float    g_dinvp[VV][NN];                      // permuted order
static __device__ __align__(16) __half g_B16[VV][NN][HH];        // B operand, PERMUTED rows
static __device__ __align__(16) __half g_h1[VV][NN][HH];         // fp16 h1, PERMUTED rows
static __device__ __align__(16) float  g_partial[KSPLIT][VV][NN][HH];  // split-K partials (75 MB)
static __device__ __align__(16) __half g_y1h[NN][2*HH];          // fusion hidden, fp16
static __device__ float    g_part[VV][NPART][HH];
static __device__ float    g_attn[VV];

__device__ __forceinline__ int perm_r(int m) {
    return ((m >> 7) << 7) | ((m & 3) << 5) | (((m >> 2) & 15) << 1) | ((m >> 6) & 1);
}

// ---- K1: pack bits (permuted word order) + degree + B16 = dinv*W1*SCALE1 ----------
__global__ void __launch_bounds__(256) k_pack(const int* __restrict__ adj,
                                              const float* __restrict__ W1) {
    const int row = blockIdx.x, v = blockIdx.y;
    const int tid = threadIdx.x, lane = tid & 31, warp = tid >> 5;
    const int4* __restrict__ arow =
        reinterpret_cast<const int4*>(adj + ((size_t)v*NN + row)*(size_t)NN);
    int cnt = 0;
    #pragma unroll
    for (int c = warp; c < 64; c += 8) {
        int4 x = __ldg(&arow[c*32 + lane]);
        int base = c*128 + lane*4;
        bool b0 = (x.x != 0) || (base + 0 == row);
        bool b1 = (x.y != 0) || (base + 1 == row);
        bool b2 = (x.z != 0) || (base + 2 == row);
        bool b3 = (x.w != 0) || (base + 3 == row);
        unsigned m0 = __ballot_sync(0xffffffffu, b0);
        unsigned m1 = __ballot_sync(0xffffffffu, b1);
        unsigned m2 = __ballot_sync(0xffffffffu, b2);
        unsigned m3 = __ballot_sync(0xffffffffu, b3);
        if (lane == 0)
            *reinterpret_cast<uint4*>(&g_packed[v][row][4*c]) = make_uint4(m0, m1, m2, m3);
        cnt += (int)b0 + (int)b1 + (int)b2 + (int)b3;
    }
    #pragma unroll
    for (int o = 16; o; o >>= 1) cnt += __shfl_xor_sync(0xffffffffu, cnt, o);
    __shared__ int sc[8];
    __shared__ float sdinv;
    if (lane == 0) sc[warp] = cnt;
    __syncthreads();
    if (tid == 0) {
        int d = 0;
        #pragma unroll
        for (int i = 0; i < 8; i++) d += sc[i];
        float di = rsqrtf((float)d);
        sdinv = di;
        g_dinv[v][row] = di;
        g_dinvp[v][perm_r(row)] = di;
    }
    __syncthreads();
    if (tid < HH) {
        int rp = perm_r(row);
        g_B16[v][rp][tid] = __float2half(W1[((size_t)v*NN + row)*HH + tid] * sdinv * SCALE1);
    }
}

// ---- mma helpers -------------------------------------------------------------------
__device__ __forceinline__ uint32_t smem_u32(const void* p) {
    return (uint32_t)__cvta_generic_to_shared(p);
}
__device__ __forceinline__ void ldsm_x4(uint32_t& r0, uint32_t& r1, uint32_t& r2, uint32_t& r3, uint32_t a) {
    asm volatile("ldmatrix.sync.aligned.m8n8.x4.shared.b16 {%0,%1,%2,%3}, [%4];"
                 : "=r"(r0), "=r"(r1), "=r"(r2), "=r"(r3) : "r"(a));
}
__device__ __forceinline__ void ldsm_x4_t(uint32_t& r0, uint32_t& r1, uint32_t& r2, uint32_t& r3, uint32_t a) {
    asm volatile("ldmatrix.sync.aligned.m8n8.x4.trans.shared.b16 {%0,%1,%2,%3}, [%4];"
                 : "=r"(r0), "=r"(r1), "=r"(r2), "=r"(r3) : "r"(a));
}
__device__ __forceinline__ void mma16816(float* c, const uint32_t* a, const uint32_t* b) {
    asm volatile("mma.sync.aligned.m16n8k16.row.col.f32.f16.f16.f32 "
                 "{%0,%1,%2,%3}, {%4,%5,%6,%7}, {%8,%9}, {%0,%1,%2,%3};"
                 : "+f"(c[0]), "+f"(c[1]), "+f"(c[2]), "+f"(c[3])
                 : "r"(a[0]), "r"(a[1]), "r"(a[2]), "r"(a[3]), "r"(b[0]), "r"(b[1]));
}
#define CP_ASYNC16(dst, src) \
    asm volatile("cp.async.cg.shared.global [%0], [%1], 16;" :: "r"(dst), "l"(src))
#define CP_COMMIT()   asm volatile("cp.async.commit_group;")
#define CP_WAIT(n)    asm volatile("cp.async.wait_group %0;" :: "n"(n))

// ---- shared mma-tile body (used by w2m/fuse kernels) -------------------------------
typedef __half MRow[136];
struct Acc { float a[2][8][4]; };
__device__ __forceinline__ void mma_chunk(Acc& A, const MRow* h1s, const MRow* w2s,
                                          int lane, int wm, int wn) {
    #pragma unroll
    for (int ks = 0; ks < 8; ks++) {
        const int k = ks * 16;
        uint32_t a[2][4];
        #pragma unroll
        for (int mt = 0; mt < 2; mt++) {
            const __half* p = &h1s[wm*32 + mt*16 + (lane & 7) + ((lane & 8) ? 8 : 0)]
                                  [k + ((lane & 16) ? 8 : 0)];
            ldsm_x4(a[mt][0], a[mt][1], a[mt][2], a[mt][3], smem_u32(p));
        }
        uint32_t b[8][2];
        #pragma unroll
        for (int nt2 = 0; nt2 < 4; nt2++) {
            int krow = k + (lane & 7) + ((lane & 8) ? 8 : 0);
            int ncol = wn*64 + nt2*16 + ((lane & 16) ? 8 : 0);
            uint32_t r0, r1, r2, r3;
            ldsm_x4_t(r0, r1, r2, r3, smem_u32(&w2s[krow][ncol]));
            b[nt2*2][0] = r0; b[nt2*2][1] = r1;
            b[nt2*2+1][0] = r2; b[nt2*2+1][1] = r3;
        }
        #pragma unroll
        for (int mt = 0; mt < 2; mt++)
            #pragma unroll
            for (int nt = 0; nt < 8; nt++)
                mma16816(A.a[mt][nt], a[mt], b[nt]);
    }
}
__device__ __forceinline__ void acc_zero(Acc& A) {
    #pragma unroll
    for (int a = 0; a < 2; a++)
        #pragma unroll
        for (int b = 0; b < 8; b++)
            #pragma unroll
            for (int c = 0; c < 4; c++) A.a[a][b][c] = 0.f;
}

// bit pair (q, q+16) of w -> fp16 {0,1} pair
__device__ __forceinline__ uint32_t bitcvt(uint32_t w, int q, __half2 c1024) {
    uint32_t t = ((w >> q) & 0x00010001u) | 0x64006400u;
    __half2 h = __hsub2(*(__half2*)&t, c1024);
    return *(uint32_t*)&h;
}

// ---- K2/K4: masked GEMM, split-K, K-chunk=128, 2x4 warp tiling, reg A frags --------
#define GEMM_SMEM (2*128*136*(int)sizeof(__half))   // 2x B buffers = 69632
__global__ void __launch_bounds__(256, 2) k_gemm(int dummy) {
    extern __shared__ char smraw[];
    MRow* Bs0 = (MRow*)smraw;
    MRow* Bs1 = (MRow*)(smraw + 128*136*sizeof(__half));
    const int v  = blockIdx.y;
    const int n0 = blockIdx.x * 128;
    const int sl = blockIdx.z;
    const int c0 = (sl * 64) / KSPLIT;
    const int c1 = ((sl + 1) * 64) / KSPLIT;
    const int tid = threadIdx.x;
    const int lane = tid & 31, warp = tid >> 5;
    const int wm = warp & 1, wn = warp >> 1;        // 2 m-halves x 4 n-quarters
    const int g = lane >> 2, l3 = lane & 3;
    const __half2 c1024 = __half2half2(__ushort_as_half(0x6400));

    float acc[4][4][4];
    #pragma unroll
    for (int a = 0; a < 4; a++)
        #pragma unroll
        for (int b = 0; b < 4; b++)
            #pragma unroll
            for (int c = 0; c < 4; c++) acc[a][b][c] = 0.f;

    // uniform base pointer: bit words of row (n0 + wm*64 + g), viewed as uint2
    const uint2* __restrict__ bp =
        reinterpret_cast<const uint2*>(g_packed[v][n0 + wm*64 + g]);
    // row (mt*16 + h*8) offset in uint2 units: (mt*16+h*8) * (WORDS/2)

    auto loadB = [&](int chunk, MRow* Bs) {
        #pragma unroll
        for (int c = 0; c < 8; c++) {
            int ch = tid + c*256;
            int kr = ch >> 4, hc = (ch & 15) * 8;
            CP_ASYNC16(smem_u32(&Bs[kr][hc]), &g_B16[v][chunk*128 + kr][hc]);
        }
        CP_COMMIT();
    };

    loadB(c0, Bs0);
    for (int i = c0; i < c1; i++) {
        MRow* Bcur = ((i - c0) & 1) ? Bs1 : Bs0;
        MRow* Bnxt = ((i - c0) & 1) ? Bs0 : Bs1;
        if (i + 1 < c1) { loadB(i + 1, Bnxt); CP_WAIT(1); }
        else            { CP_WAIT(0); }
        __syncthreads();

        #pragma unroll
        for (int half = 0; half < 2; half++) {
            // words 4i + half*2, 4i + half*2 + 1 for each of 8 rows
            uint2 Wp[4][2];
            #pragma unroll
            for (int mt = 0; mt < 4; mt++)
                #pragma unroll
                for (int h = 0; h < 2; h++)
                    Wp[mt][h] = __ldg(&bp[(mt*16 + h*8)*(WORDS/2) + 2*i + half]);
            #pragma unroll
            for (int kl = 0; kl < 4; kl++) {
                const int ks = half*4 + kl;
                const int k = ks * 16;
                const int jj = kl >> 1;                 // which word of the pair
                const int q0 = (ks & 1) * 8 + l3;
                uint32_t a[4][4];
                #pragma unroll
                for (int mt = 0; mt < 4; mt++) {
                    uint32_t w0 = jj ? Wp[mt][0].y : Wp[mt][0].x;
                    uint32_t w1 = jj ? Wp[mt][1].y : Wp[mt][1].x;
                    a[mt][0] = bitcvt(w0, q0,     c1024);
                    a[mt][1] = bitcvt(w1, q0,     c1024);
                    a[mt][2] = bitcvt(w0, q0 + 4, c1024);
                    a[mt][3] = bitcvt(w1, q0 + 4, c1024);
                }
                uint32_t b[4][2];
                #pragma unroll
                for (int nt2 = 0; nt2 < 2; nt2++) {
                    int krow = k + (lane & 7) + ((lane & 8) ? 8 : 0);
                    int ncol = wn*32 + nt2*16 + ((lane & 16) ? 8 : 0);
                    uint32_t r0, r1, r2, r3;
                    ldsm_x4_t(r0, r1, r2, r3, smem_u32(&Bcur[krow][ncol]));
                    b[nt2*2][0] = r0; b[nt2*2][1] = r1;
                    b[nt2*2+1][0] = r2; b[nt2*2+1][1] = r3;
                }
                #pragma unroll
                for (int mt = 0; mt < 4; mt++)
                    #pragma unroll
                    for (int nt = 0; nt < 4; nt++)
                        mma16816(acc[mt][nt], a[mt], b[nt]);
            }
        }
        __syncthreads();
    }

    const int cp2 = l3 * 2;
    float* pp = &g_partial[sl][v][0][0];
    #pragma unroll
    for (int mt = 0; mt < 4; mt++) {
        int nl0 = n0 + wm*64 + mt*16 + g, nl1 = nl0 + 8;
        #pragma unroll
        for (int nt = 0; nt < 4; nt++) {
            int cc = wn*32 + nt*8 + cp2;
            *reinterpret_cast<float2*>(&pp[(size_t)nl0*HH + cc]) =
                make_float2(acc[mt][nt][0], acc[mt][nt][1]);
            *reinterpret_cast<float2*>(&pp[(size_t)nl1*HH + cc]) =
                make_float2(acc[mt][nt][2], acc[mt][nt][3]);
        }
    }
    (void)dummy;
}

// ---- K3/K5: reduce split-K partials + epilogue -------------------------------------
__global__ void __launch_bounds__(256) k_red(const float* __restrict__ bias,
                                             float* __restrict__ outp,
                                             float invscale, int mode) {
    const int v = blockIdx.y, n0 = blockIdx.x * 128;
    const int tid = threadIdx.x;
    const int row = n0 + (tid >> 1);
    const int cb  = (tid & 1) * 64;
    const float dsc = g_dinv[v][row] * invscale;
    const size_t off = ((size_t)v*NN + row)*HH + cb;
    const size_t sstr = (size_t)VV*NN*HH;
    const float* p0 = &g_partial[0][0][0][0] + off;
    const int rp = perm_r(row);
    float* orow = (mode == 1) ? (outp + ((size_t)v*NN + row)*HH) : nullptr;
    #pragma unroll
    for (int j = 0; j < 64; j += 4) {
        float4 s = *reinterpret_cast<const float4*>(p0 + j);
        #pragma unroll
        for (int sl = 1; sl < KSPLIT; sl++) {
            float4 t = *reinterpret_cast<const float4*>(p0 + sl*sstr + j);
            s.x += t.x; s.y += t.y; s.z += t.z; s.w += t.w;
        }
        int col = cb + j;
        float r0 = fmaxf(fmaf(dsc, s.x, bias[v*HH + col    ]), 0.f);
        float r1 = fmaxf(fmaf(dsc, s.y, bias[v*HH + col + 1]), 0.f);
        float r2 = fmaxf(fmaf(dsc, s.z, bias[v*HH + col + 2]), 0.f);
        float r3 = fmaxf(fmaf(dsc, s.w, bias[v*HH + col + 3]), 0.f);
        if (mode == 0) {
            *reinterpret_cast<__half2*>(&g_h1[v][rp][col])     = __floats2half2_rn(r0, r1);
            *reinterpret_cast<__half2*>(&g_h1[v][rp][col + 2]) = __floats2half2_rn(r2, r3);
        } else {
            orow[col]     = r0;   // d_out region only 4B-aligned -> scalar stores
            orow[col + 1] = r1;
            orow[col + 2] = r2;
            orow[col + 3] = r3;
        }
    }
}

// ---- K4b: B16 = dinvp * SCALE2 * (h1 @ W2), permuted row space ---------------------
#define MMA_SMEM (2*128*136*(int)sizeof(__half))
__global__ void __launch_bounds__(256) k_w2m(const float* __restrict__ W2) {
    extern __shared__ char smraw[];
    MRow* h1s = (MRow*)smraw;
    MRow* w2s = (MRow*)(smraw + 128*136*sizeof(__half));
    const int v = blockIdx.y, n0 = blockIdx.x * 128;
    const int tid = threadIdx.x, lane = tid & 31, warp = tid >> 5;
    const int wm = warp & 3, wn = warp >> 2;

    #pragma unroll
    for (int c = 0; c < 8; c++) {
        int e = tid + c*256;
        int r = e >> 4, u = e & 15;
        *reinterpret_cast<uint4*>(&h1s[r][u*8]) =
            *reinterpret_cast<const uint4*>(&g_h1[v][n0 + r][u*8]);
    }
    #pragma unroll
    for (int c = 0; c < 32; c++) {
        int e = tid + c*256;
        int h = e >> 6, p = e & 63;
        float2 f = *reinterpret_cast<const float2*>(&W2[((size_t)v*HH + h)*HH + p*2]);
        *reinterpret_cast<__half2*>(&w2s[h][p*2]) = __floats2half2_rn(f.x, f.y);
    }
    __syncthreads();

    Acc A; acc_zero(A);
    mma_chunk(A, h1s, w2s, lane, wm, wn);

    const int g = lane >> 2, cp2 = (lane & 3) * 2;
    #pragma unroll
    for (int mt = 0; mt < 2; mt++) {
        int r0 = n0 + wm*32 + mt*16 + g, r1 = r0 + 8;
        float d0 = g_dinvp[v][r0] * SCALE2;
        float d1 = g_dinvp[v][r1] * SCALE2;
        #pragma unroll
        for (int nt = 0; nt < 8; nt++) {
            int c0 = wn*64 + nt*8 + cp2;
            *reinterpret_cast<__half2*>(&g_B16[v][r0][c0]) =
                __floats2half2_rn(A.a[mt][nt][0]*d0, A.a[mt][nt][1]*d0);
            *reinterpret_cast<__half2*>(&g_B16[v][r1][c0]) =
                __floats2half2_rn(A.a[mt][nt][2]*d1, A.a[mt][nt][3]*d1);
        }
    }
}

// ---- K6: mean-pool partials --------------------------------------------------------
__global__ void __launch_bounds__(128) k_part(const float* __restrict__ hmat) {
    const int p = blockIdx.x, v = blockIdx.y, h = threadIdx.x;
    float s = 0.f;
    const int span = NN / NPART;
    for (int n = p*span; n < (p+1)*span; n++)
        s += hmat[((size_t)v*NN + n)*HH + h];
    g_part[v][p][h] = s;
}

// ---- K7: summaries + attention softmax ---------------------------------------------
__global__ void __launch_bounds__(128) k_summ_attn(const float* __restrict__ Wa1,
                                                   const float* __restrict__ ba1,
                                                   const float* __restrict__ Wa2,
                                                   const float* __restrict__ ba2,
                                                   float* __restrict__ outattn) {
    __shared__ float summ[VV][HH];
    __shared__ float s1[ADIM];
    __shared__ float sc[VV];
    const int tid = threadIdx.x;
    #pragma unroll
    for (int v = 0; v < VV; v++) {
        float s = 0.f;
        #pragma unroll
        for (int p = 0; p < NPART; p++) s += g_part[v][p][tid];
        summ[v][tid] = s * (1.0f / (float)NN);
    }
    __syncthreads();
    for (int v = 0; v < VV; v++) {
        if (tid < ADIM) {
            float a = ba1[tid];
            for (int hh = 0; hh < HH; hh++) a = fmaf(summ[v][hh], Wa1[hh*ADIM + tid], a);
            s1[tid] = tanhf(a);
        }
        __syncthreads();
        if (tid == 0) {
            float sv = ba2[0];
            for (int j = 0; j < ADIM; j++) sv = fmaf(s1[j], Wa2[j], sv);
            sc[v] = sv;
        }
        __syncthreads();
    }
    if (tid == 0) {
        float m = fmaxf(sc[0], fmaxf(sc[1], sc[2]));
        float e0 = expf(sc[0]-m), e1 = expf(sc[1]-m), e2 = expf(sc[2]-m);
        float inv = 1.f / (e0 + e1 + e2);
        g_attn[0] = e0*inv; g_attn[1] = e1*inv; g_attn[2] = e2*inv;
        outattn[0] = e0*inv; outattn[1] = e1*inv; outattn[2] = e2*inv;
    }
}

// ---- K8: y1h = fp16(relu([h*attn] @ Wf1 + bf1)), tensor-core -----------------------
__global__ void __launch_bounds__(256) k_fuse1m(const float* __restrict__ hsrc,
                                                const float* __restrict__ Wf1,
                                                const float* __restrict__ bf1) {
    extern __shared__ char smraw[];
    MRow* h1s = (MRow*)smraw;
    MRow* w2s = (MRow*)(smraw + 128*136*sizeof(__half));
    const int n0 = blockIdx.x * 128;
    const int cb = blockIdx.y * 128;
    const int tid = threadIdx.x, lane = tid & 31, warp = tid >> 5;
    const int wm = warp & 3, wn = warp >> 2;

    Acc A; acc_zero(A);
    for (int v = 0; v < VV; v++) {
        float av = g_attn[v];
        const float* hs = hsrc + (size_t)v*NN*HH + (size_t)n0*HH;
        for (int idx = tid; idx < 128*128; idx += 256) {
            int r = idx >> 7, c = idx & 127;
            h1s[r][c] = __float2half(hs[(size_t)r*HH + c] * av);
        }
        #pragma unroll
        for (int c = 0; c < 32; c++) {
            int e = tid + c*256;
            int h = e >> 6, p = e & 63;
            float2 f = *reinterpret_cast<const float2*>(&Wf1[((size_t)(v*128 + h))*(2*HH) + cb + p*2]);
            *reinterpret_cast<__half2*>(&w2s[h][p*2]) = __floats2half2_rn(f.x, f.y);
        }
        __syncthreads();
        mma_chunk(A, h1s, w2s, lane, wm, wn);
        __syncthreads();
    }

    const int g = lane >> 2, cp2 = (lane & 3) * 2;
    #pragma unroll
    for (int mt = 0; mt < 2; mt++) {
        int r0 = n0 + wm*32 + mt*16 + g, r1 = r0 + 8;
        #pragma unroll
        for (int nt = 0; nt < 8; nt++) {
            int c0 = wn*64 + nt*8 + cp2;
            float b0 = bf1[cb + c0], b1 = bf1[cb + c0 + 1];
            *reinterpret_cast<__half2*>(&g_y1h[r0][cb + c0]) =
                __floats2half2_rn(fmaxf(A.a[mt][nt][0] + b0, 0.f), fmaxf(A.a[mt][nt][1] + b1, 0.f));
            *reinterpret_cast<__half2*>(&g_y1h[r1][cb + c0]) =
                __floats2half2_rn(fmaxf(A.a[mt][nt][2] + b0, 0.f), fmaxf(A.a[mt][nt][3] + b1, 0.f));
        }
    }
}

// ---- K9: fused = y1h @ Wf2 + bf2, tensor-core --------------------------------------
__global__ void __launch_bounds__(256) k_fuse2m(const float* __restrict__ Wf2,
                                                const float* __restrict__ bf2,
                                                float* __restrict__ outf) {
    extern __shared__ char smraw[];
    MRow* h1s = (MRow*)smraw;
    MRow* w2s = (MRow*)(smraw + 128*136*sizeof(__half));
    const int n0 = blockIdx.x * 128;
    const int tid = threadIdx.x, lane = tid & 31, warp = tid >> 5;
    const int wm = warp & 3, wn = warp >> 2;

    Acc A; acc_zero(A);
    for (int kk = 0; kk < 2; kk++) {
        #pragma unroll
        for (int c = 0; c < 8; c++) {
            int e = tid + c*256;
            int r = e >> 4, u = e & 15;
            *reinterpret_cast<uint4*>(&h1s[r][u*8]) =
                *reinterpret_cast<const uint4*>(&g_y1h[n0 + r][kk*128 + u*8]);
        }
        #pragma unroll
        for (int c = 0; c < 32; c++) {
            int e = tid + c*256;
            int h = e >> 6, p = e & 63;
            float2 f = *reinterpret_cast<const float2*>(&Wf2[((size_t)(kk*128 + h))*FOUT + p*2]);
            *reinterpret_cast<__half2*>(&w2s[h][p*2]) = __floats2half2_rn(f.x, f.y);
        }
        __syncthreads();
        mma_chunk(A, h1s, w2s, lane, wm, wn);
        __syncthreads();
    }

    const int g = lane >> 2, cp2 = (lane & 3) * 2;
    #pragma unroll
    for (int mt = 0; mt < 2; mt++) {
        int r0 = n0 + wm*32 + mt*16 + g, r1 = r0 + 8;
        #pragma unroll
        for (int nt = 0; nt < 8; nt++) {
            int c0 = wn*64 + nt*8 + cp2;
            float b0 = bf2[c0], b1 = bf2[c0 + 1];
            *reinterpret_cast<float2*>(&outf[(size_t)r0*FOUT + c0]) =
                make_float2(A.a[mt][nt][0] + b0, A.a[mt][nt][1] + b1);
            *reinterpret_cast<float2*>(&outf[(size_t)r1*FOUT + c0]) =
                make_float2(A.a[mt][nt][2] + b0, A.a[mt][nt][3] + b1);
        }
    }
}

// ---- launch ------------------------------------------------------------------------
extern "C" void kernel_launch(void* const* d_in, const int* in_sizes, int n_in,
                              void* d_out, int out_size) {
    const int*   adj = (const int*)  d_in[0];
    const float* W1  = (const float*)d_in[1];
    const float* b1  = (const float*)d_in[2];
    const float* W2  = (const float*)d_in[3];
    const float* b2  = (const float*)d_in[4];
    const float* Wa1 = (const float*)d_in[5];
    const float* ba1 = (const float*)d_in[6];
    const float* Wa2 = (const float*)d_in[7];
    const float* ba2 = (const float*)d_in[8];
    const float* Wf1 = (const float*)d_in[9];
    const float* bf1 = (const float*)d_in[10];
    const float* Wf2 = (const float*)d_in[11];
    const float* bf2 = (const float*)d_in[12];

    float* out       = (float*)d_out;
    float* out_fused = out;                                   // (N, F_OUT) — base 16B aligned
    float* out_attn  = out + (size_t)NN * FOUT;               // (V,)
    float* out_h     = out + (size_t)NN * FOUT + VV;          // (V, N, H) — only 4B aligned

    static int configured = 0;
    if (!configured) {
        cudaFuncSetAttribute(k_gemm,   cudaFuncAttributeMaxDynamicSharedMemorySize, GEMM_SMEM);
        cudaFuncSetAttribute(k_w2m,    cudaFuncAttributeMaxDynamicSharedMemorySize, MMA_SMEM);
        cudaFuncSetAttribute(k_fuse1m, cudaFuncAttributeMaxDynamicSharedMemorySize, MMA_SMEM);
        cudaFuncSetAttribute(k_fuse2m, cudaFuncAttributeMaxDynamicSharedMemorySize, MMA_SMEM);
        configured = 1;
    }

    k_pack<<<dim3(NN, VV), 256>>>(adj, W1);
    k_gemm<<<dim3(NN/128, VV, KSPLIT), 256, GEMM_SMEM>>>(0);
    k_red<<<dim3(NN/128, VV), 256>>>(b1, nullptr, 1.0f/SCALE1, 0);
    k_w2m<<<dim3(NN/128, VV), 256, MMA_SMEM>>>(W2);
    k_gemm<<<dim3(NN/128, VV, KSPLIT), 256, GEMM_SMEM>>>(0);
    k_red<<<dim3(NN/128, VV), 256>>>(b2, out_h, 1.0f/SCALE2, 1);
    k_part<<<dim3(NPART, VV), 128>>>(out_h);
    k_summ_attn<<<1, 128>>>(Wa1, ba1, Wa2, ba2, out_attn);
    k_fuse1m<<<dim3(NN/128, 2), 256, MMA_SMEM>>>(out_h, Wf1, bf1);
    k_fuse2m<<<NN/128, 256, MMA_SMEM>>>(Wf2, bf2, out_fused);
}

// round 13
// speedup vs baseline: 1.1390x; 1.1390x over previous
#include <cuda_runtime.h>
#include <cuda_fp16.h>
#include <stdint.h>

#define VV 3
#define NN 8192
#define HH 128
#define ADIM 64
#define FOUT 128
#define WORDS 256
#define SCALE1 256.0f
#define SCALE2 1024.0f
#define KSPLIT 6
#define NPART 64

static __device__ uint32_t g_packed[VV][NN][WORDS];              // word 4c+k, bit l <-> col 128c+4l+k
static __device__ float    g_dinv[VV][NN];                       // natural order
static __device__ float    g_dinvp[VV][NN];                      // permuted order
static __device__ __align__(16) __half g_B16[VV][NN][HH];        // B operand, PERMUTED rows
static __device__ __align__(16) __half g_h1[VV][NN][HH];         // fp16 h1, PERMUTED rows
static __device__ __align__(16) float  g_partial[KSPLIT][VV][NN][HH];  // split-K partials (75 MB)
static __device__ __align__(16) __half g_y1h[NN][2*HH];          // fusion hidden, fp16
static __device__ float    g_part[VV][NPART][HH];
static __device__ float    g_attn[VV];

__device__ __forceinline__ int perm_r(int m) {
    return ((m >> 7) << 7) | ((m & 3) << 5) | (((m >> 2) & 15) << 1) | ((m >> 6) & 1);
}

// ---- K1: pack bits (permuted word order) + degree + B16 = dinv*W1*SCALE1 ----------
__global__ void __launch_bounds__(256) k_pack(const int* __restrict__ adj,
                                              const float* __restrict__ W1) {
    const int row = blockIdx.x, v = blockIdx.y;
    const int tid = threadIdx.x, lane = tid & 31, warp = tid >> 5;
    const int4* __restrict__ arow =
        reinterpret_cast<const int4*>(adj + ((size_t)v*NN + row)*(size_t)NN);
    int cnt = 0;
    #pragma unroll
    for (int c = warp; c < 64; c += 8) {
        int4 x = __ldg(&arow[c*32 + lane]);
        int base = c*128 + lane*4;
        bool b0 = (x.x != 0) || (base + 0 == row);
        bool b1 = (x.y != 0) || (base + 1 == row);
        bool b2 = (x.z != 0) || (base + 2 == row);
        bool b3 = (x.w != 0) || (base + 3 == row);
        unsigned m0 = __ballot_sync(0xffffffffu, b0);
        unsigned m1 = __ballot_sync(0xffffffffu, b1);
        unsigned m2 = __ballot_sync(0xffffffffu, b2);
        unsigned m3 = __ballot_sync(0xffffffffu, b3);
        if (lane == 0)
            *reinterpret_cast<uint4*>(&g_packed[v][row][4*c]) = make_uint4(m0, m1, m2, m3);
        cnt += (int)b0 + (int)b1 + (int)b2 + (int)b3;
    }
    #pragma unroll
    for (int o = 16; o; o >>= 1) cnt += __shfl_xor_sync(0xffffffffu, cnt, o);
    __shared__ int sc[8];
    __shared__ float sdinv;
    if (lane == 0) sc[warp] = cnt;
    __syncthreads();
    if (tid == 0) {
        int d = 0;
        #pragma unroll
        for (int i = 0; i < 8; i++) d += sc[i];
        float di = rsqrtf((float)d);
        sdinv = di;
        g_dinv[v][row] = di;
        g_dinvp[v][perm_r(row)] = di;
    }
    __syncthreads();
    if (tid < HH) {
        int rp = perm_r(row);
        g_B16[v][rp][tid] = __float2half(W1[((size_t)v*NN + row)*HH + tid] * sdinv * SCALE1);
    }
}

// ---- mma helpers -------------------------------------------------------------------
__device__ __forceinline__ uint32_t smem_u32(const void* p) {
    return (uint32_t)__cvta_generic_to_shared(p);
}
__device__ __forceinline__ void ldsm_x4(uint32_t& r0, uint32_t& r1, uint32_t& r2, uint32_t& r3, uint32_t a) {
    asm volatile("ldmatrix.sync.aligned.m8n8.x4.shared.b16 {%0,%1,%2,%3}, [%4];"
                 : "=r"(r0), "=r"(r1), "=r"(r2), "=r"(r3) : "r"(a));
}
__device__ __forceinline__ void ldsm_x4_t(uint32_t& r0, uint32_t& r1, uint32_t& r2, uint32_t& r3, uint32_t a) {
    asm volatile("ldmatrix.sync.aligned.m8n8.x4.trans.shared.b16 {%0,%1,%2,%3}, [%4];"
                 : "=r"(r0), "=r"(r1), "=r"(r2), "=r"(r3) : "r"(a));
}
__device__ __forceinline__ void mma16816(float* c, const uint32_t* a, const uint32_t* b) {
    asm volatile("mma.sync.aligned.m16n8k16.row.col.f32.f16.f16.f32 "
                 "{%0,%1,%2,%3}, {%4,%5,%6,%7}, {%8,%9}, {%0,%1,%2,%3};"
                 : "+f"(c[0]), "+f"(c[1]), "+f"(c[2]), "+f"(c[3])
                 : "r"(a[0]), "r"(a[1]), "r"(a[2]), "r"(a[3]), "r"(b[0]), "r"(b[1]));
}
#define CP_ASYNC16(dst, src) \
    asm volatile("cp.async.cg.shared.global [%0], [%1], 16;" :: "r"(dst), "l"(src))
#define CP_COMMIT()   asm volatile("cp.async.commit_group;")
#define CP_WAIT(n)    asm volatile("cp.async.wait_group %0;" :: "n"(n))

// ---- shared mma-tile body (used by w2m/fuse kernels) -------------------------------
typedef __half MRow[136];
struct Acc { float a[2][8][4]; };
__device__ __forceinline__ void mma_chunk(Acc& A, const MRow* h1s, const MRow* w2s,
                                          int lane, int wm, int wn) {
    #pragma unroll
    for (int ks = 0; ks < 8; ks++) {
        const int k = ks * 16;
        uint32_t a[2][4];
        #pragma unroll
        for (int mt = 0; mt < 2; mt++) {
            const __half* p = &h1s[wm*32 + mt*16 + (lane & 7) + ((lane & 8) ? 8 : 0)]
                                  [k + ((lane & 16) ? 8 : 0)];
            ldsm_x4(a[mt][0], a[mt][1], a[mt][2], a[mt][3], smem_u32(p));
        }
        uint32_t b[8][2];
        #pragma unroll
        for (int nt2 = 0; nt2 < 4; nt2++) {
            int krow = k + (lane & 7) + ((lane & 8) ? 8 : 0);
            int ncol = wn*64 + nt2*16 + ((lane & 16) ? 8 : 0);
            uint32_t r0, r1, r2, r3;
            ldsm_x4_t(r0, r1, r2, r3, smem_u32(&w2s[krow][ncol]));
            b[nt2*2][0] = r0; b[nt2*2][1] = r1;
            b[nt2*2+1][0] = r2; b[nt2*2+1][1] = r3;
        }
        #pragma unroll
        for (int mt = 0; mt < 2; mt++)
            #pragma unroll
            for (int nt = 0; nt < 8; nt++)
                mma16816(A.a[mt][nt], a[mt], b[nt]);
    }
}
__device__ __forceinline__ void acc_zero(Acc& A) {
    #pragma unroll
    for (int a = 0; a < 2; a++)
        #pragma unroll
        for (int b = 0; b < 8; b++)
            #pragma unroll
            for (int c = 0; c < 4; c++) A.a[a][b][c] = 0.f;
}

// bit pair (q, q+16) of w -> fp16 {0,1} pair
__device__ __forceinline__ uint32_t bitcvt(uint32_t w, int q, __half2 c1024) {
    uint32_t t = ((w >> q) & 0x00010001u) | 0x64006400u;
    __half2 h = __hsub2(*(__half2*)&t, c1024);
    return *(uint32_t*)&h;
}

// ---- K2/K4: masked GEMM, split-K, K-chunk=128, 4x2 tiling, reg A frags,
// ----        3-stage B ring with ONE barrier per chunk ------------------------------
#define GEMM_SMEM (3*128*136*(int)sizeof(__half))   // 3x B buffers = 104448
__global__ void __launch_bounds__(256, 2) k_gemm(int dummy) {
    extern __shared__ char smraw[];
    const int v  = blockIdx.y;
    const int n0 = blockIdx.x * 128;
    const int sl = blockIdx.z;
    const int c0 = (sl * 64) / KSPLIT;
    const int c1 = ((sl + 1) * 64) / KSPLIT;
    const int tid = threadIdx.x;
    const int lane = tid & 31, warp = tid >> 5;
    const int wm = warp & 3, wn = warp >> 2;
    const int g = lane >> 2, l3 = lane & 3;
    const __half2 c1024 = __half2half2(__ushort_as_half(0x6400));

    Acc A; acc_zero(A);
    const uint4* rowp[2][2];
    #pragma unroll
    for (int mt = 0; mt < 2; mt++)
        #pragma unroll
        for (int h = 0; h < 2; h++)
            rowp[mt][h] = reinterpret_cast<const uint4*>(
                g_packed[v][n0 + wm*32 + mt*16 + h*8 + g]);

    auto loadB = [&](int chunk, int buf) {
        MRow* Bs = (MRow*)(smraw + (size_t)buf*128*136*sizeof(__half));
        #pragma unroll
        for (int c = 0; c < 8; c++) {
            int ch = tid + c*256;
            int kr = ch >> 4, hc = (ch & 15) * 8;
            CP_ASYNC16(smem_u32(&Bs[kr][hc]), &g_B16[v][chunk*128 + kr][hc]);
        }
        CP_COMMIT();
    };

    loadB(c0, 0);
    for (int i = c0; i < c1; i++) {
        const int bi = (i - c0) % 3;
        MRow* Bcur = (MRow*)(smraw + (size_t)bi*128*136*sizeof(__half));
        // bit words for chunk i (register A fragments)
        uint32_t W[2][2][4];
        #pragma unroll
        for (int mt = 0; mt < 2; mt++)
            #pragma unroll
            for (int h = 0; h < 2; h++) {
                uint4 u = __ldg(&rowp[mt][h][i]);
                W[mt][h][0] = u.x; W[mt][h][1] = u.y; W[mt][h][2] = u.z; W[mt][h][3] = u.w;
            }
        if (i + 1 < c1) { loadB(i + 1, (i + 1 - c0) % 3); CP_WAIT(1); }
        else            { CP_WAIT(0); }
        __syncthreads();   // single barrier: publishes chunk i's B; also fences ring reuse

        #pragma unroll
        for (int ks = 0; ks < 8; ks++) {
            const int k = ks * 16;
            const int j  = ks >> 1;
            const int q0 = (ks & 1) * 8 + l3;
            uint32_t a[2][4];
            #pragma unroll
            for (int mt = 0; mt < 2; mt++) {
                a[mt][0] = bitcvt(W[mt][0][j], q0,     c1024);
                a[mt][1] = bitcvt(W[mt][1][j], q0,     c1024);
                a[mt][2] = bitcvt(W[mt][0][j], q0 + 4, c1024);
                a[mt][3] = bitcvt(W[mt][1][j], q0 + 4, c1024);
            }
            uint32_t b[8][2];
            #pragma unroll
            for (int nt2 = 0; nt2 < 4; nt2++) {
                int krow = k + (lane & 7) + ((lane & 8) ? 8 : 0);
                int ncol = wn*64 + nt2*16 + ((lane & 16) ? 8 : 0);
                uint32_t r0, r1, r2, r3;
                ldsm_x4_t(r0, r1, r2, r3, smem_u32(&Bcur[krow][ncol]));
                b[nt2*2][0] = r0; b[nt2*2][1] = r1;
                b[nt2*2+1][0] = r2; b[nt2*2+1][1] = r3;
            }
            #pragma unroll
            for (int mt = 0; mt < 2; mt++)
                #pragma unroll
                for (int nt = 0; nt < 8; nt++)
                    mma16816(A.a[mt][nt], a[mt], b[nt]);
        }
        // no trailing barrier: 3-stage ring guarantees buffer (i+2)%3 != (i)%3,
        // and the next iteration's barrier orders reuse of buffer (i-1)%3.
    }

    const int cp2 = l3 * 2;
    float* pp = &g_partial[sl][v][0][0];
    #pragma unroll
    for (int mt = 0; mt < 2; mt++) {
        int nl0 = n0 + wm*32 + mt*16 + g, nl1 = nl0 + 8;
        #pragma unroll
        for (int nt = 0; nt < 8; nt++) {
            int cc = wn*64 + nt*8 + cp2;
            *reinterpret_cast<float2*>(&pp[(size_t)nl0*HH + cc]) =
                make_float2(A.a[mt][nt][0], A.a[mt][nt][1]);
            *reinterpret_cast<float2*>(&pp[(size_t)nl1*HH + cc]) =
                make_float2(A.a[mt][nt][2], A.a[mt][nt][3]);
        }
    }
    (void)dummy;
}

// ---- K3/K5: reduce split-K partials + epilogue -------------------------------------
__global__ void __launch_bounds__(256) k_red(const float* __restrict__ bias,
                                             float* __restrict__ outp,
                                             float invscale, int mode) {
    const int v = blockIdx.y, n0 = blockIdx.x * 128;
    const int tid = threadIdx.x;
    const int row = n0 + (tid >> 1);
    const int cb  = (tid & 1) * 64;
    const float dsc = g_dinv[v][row] * invscale;
    const size_t off = ((size_t)v*NN + row)*HH + cb;
    const size_t sstr = (size_t)VV*NN*HH;
    const float* p0 = &g_partial[0][0][0][0] + off;
    const int rp = perm_r(row);
    float* orow = (mode == 1) ? (outp + ((size_t)v*NN + row)*HH) : nullptr;
    #pragma unroll
    for (int j = 0; j < 64; j += 4) {
        float4 s = *reinterpret_cast<const float4*>(p0 + j);
        #pragma unroll
        for (int sl = 1; sl < KSPLIT; sl++) {
            float4 t = *reinterpret_cast<const float4*>(p0 + sl*sstr + j);
            s.x += t.x; s.y += t.y; s.z += t.z; s.w += t.w;
        }
        int col = cb + j;
        float r0 = fmaxf(fmaf(dsc, s.x, bias[v*HH + col    ]), 0.f);
        float r1 = fmaxf(fmaf(dsc, s.y, bias[v*HH + col + 1]), 0.f);
        float r2 = fmaxf(fmaf(dsc, s.z, bias[v*HH + col + 2]), 0.f);
        float r3 = fmaxf(fmaf(dsc, s.w, bias[v*HH + col + 3]), 0.f);
        if (mode == 0) {
            *reinterpret_cast<__half2*>(&g_h1[v][rp][col])     = __floats2half2_rn(r0, r1);
            *reinterpret_cast<__half2*>(&g_h1[v][rp][col + 2]) = __floats2half2_rn(r2, r3);
        } else {
            orow[col]     = r0;   // d_out region only 4B-aligned -> scalar stores
            orow[col + 1] = r1;
            orow[col + 2] = r2;
            orow[col + 3] = r3;
        }
    }
}

// ---- K4b: B16 = dinvp * SCALE2 * (h1 @ W2), permuted row space ---------------------
#define MMA_SMEM (2*128*136*(int)sizeof(__half))
__global__ void __launch_bounds__(256) k_w2m(const float* __restrict__ W2) {
    extern __shared__ char smraw[];
    MRow* h1s = (MRow*)smraw;
    MRow* w2s = (MRow*)(smraw + 128*136*sizeof(__half));
    const int v = blockIdx.y, n0 = blockIdx.x * 128;
    const int tid = threadIdx.x, lane = tid & 31, warp = tid >> 5;
    const int wm = warp & 3, wn = warp >> 2;

    #pragma unroll
    for (int c = 0; c < 8; c++) {
        int e = tid + c*256;
        int r = e >> 4, u = e & 15;
        *reinterpret_cast<uint4*>(&h1s[r][u*8]) =
            *reinterpret_cast<const uint4*>(&g_h1[v][n0 + r][u*8]);
    }
    #pragma unroll
    for (int c = 0; c < 32; c++) {
        int e = tid + c*256;
        int h = e >> 6, p = e & 63;
        float2 f = *reinterpret_cast<const float2*>(&W2[((size_t)v*HH + h)*HH + p*2]);
        *reinterpret_cast<__half2*>(&w2s[h][p*2]) = __floats2half2_rn(f.x, f.y);
    }
    __syncthreads();

    Acc A; acc_zero(A);
    mma_chunk(A, h1s, w2s, lane, wm, wn);

    const int g = lane >> 2, cp2 = (lane & 3) * 2;
    #pragma unroll
    for (int mt = 0; mt < 2; mt++) {
        int r0 = n0 + wm*32 + mt*16 + g, r1 = r0 + 8;
        float d0 = g_dinvp[v][r0] * SCALE2;
        float d1 = g_dinvp[v][r1] * SCALE2;
        #pragma unroll
        for (int nt = 0; nt < 8; nt++) {
            int c0 = wn*64 + nt*8 + cp2;
            *reinterpret_cast<__half2*>(&g_B16[v][r0][c0]) =
                __floats2half2_rn(A.a[mt][nt][0]*d0, A.a[mt][nt][1]*d0);
            *reinterpret_cast<__half2*>(&g_B16[v][r1][c0]) =
                __floats2half2_rn(A.a[mt][nt][2]*d1, A.a[mt][nt][3]*d1);
        }
    }
}

// ---- K6: mean-pool partials --------------------------------------------------------
__global__ void __launch_bounds__(128) k_part(const float* __restrict__ hmat) {
    const int p = blockIdx.x, v = blockIdx.y, h = threadIdx.x;
    float s = 0.f;
    const int span = NN / NPART;
    for (int n = p*span; n < (p+1)*span; n++)
        s += hmat[((size_t)v*NN + n)*HH + h];
    g_part[v][p][h] = s;
}

// ---- K7: summaries + attention softmax ---------------------------------------------
__global__ void __launch_bounds__(128) k_summ_attn(const float* __restrict__ Wa1,
                                                   const float* __restrict__ ba1,
                                                   const float* __restrict__ Wa2,
                                                   const float* __restrict__ ba2,
                                                   float* __restrict__ outattn) {
    __shared__ float summ[VV][HH];
    __shared__ float s1[ADIM];
    __shared__ float sc[VV];
    const int tid = threadIdx.x;
    #pragma unroll
    for (int v = 0; v < VV; v++) {
        float s = 0.f;
        #pragma unroll
        for (int p = 0; p < NPART; p++) s += g_part[v][p][tid];
        summ[v][tid] = s * (1.0f / (float)NN);
    }
    __syncthreads();
    for (int v = 0; v < VV; v++) {
        if (tid < ADIM) {
            float a = ba1[tid];
            for (int hh = 0; hh < HH; hh++) a = fmaf(summ[v][hh], Wa1[hh*ADIM + tid], a);
            s1[tid] = tanhf(a);
        }
        __syncthreads();
        if (tid == 0) {
            float sv = ba2[0];
            for (int j = 0; j < ADIM; j++) sv = fmaf(s1[j], Wa2[j], sv);
            sc[v] = sv;
        }
        __syncthreads();
    }
    if (tid == 0) {
        float m = fmaxf(sc[0], fmaxf(sc[1], sc[2]));
        float e0 = expf(sc[0]-m), e1 = expf(sc[1]-m), e2 = expf(sc[2]-m);
        float inv = 1.f / (e0 + e1 + e2);
        g_attn[0] = e0*inv; g_attn[1] = e1*inv; g_attn[2] = e2*inv;
        outattn[0] = e0*inv; outattn[1] = e1*inv; outattn[2] = e2*inv;
    }
}

// ---- K8: y1h = fp16(relu([h*attn] @ Wf1 + bf1)), tensor-core -----------------------
__global__ void __launch_bounds__(256) k_fuse1m(const float* __restrict__ hsrc,
                                                const float* __restrict__ Wf1,
                                                const float* __restrict__ bf1) {
    extern __shared__ char smraw[];
    MRow* h1s = (MRow*)smraw;
    MRow* w2s = (MRow*)(smraw + 128*136*sizeof(__half));
    const int n0 = blockIdx.x * 128;
    const int cb = blockIdx.y * 128;
    const int tid = threadIdx.x, lane = tid & 31, warp = tid >> 5;
    const int wm = warp & 3, wn = warp >> 2;

    Acc A; acc_zero(A);
    for (int v = 0; v < VV; v++) {
        float av = g_attn[v];
        const float* hs = hsrc + (size_t)v*NN*HH + (size_t)n0*HH;
        for (int idx = tid; idx < 128*128; idx += 256) {
            int r = idx >> 7, c = idx & 127;
            h1s[r][c] = __float2half(hs[(size_t)r*HH + c] * av);
        }
        #pragma unroll
        for (int c = 0; c < 32; c++) {
            int e = tid + c*256;
            int h = e >> 6, p = e & 63;
            float2 f = *reinterpret_cast<const float2*>(&Wf1[((size_t)(v*128 + h))*(2*HH) + cb + p*2]);
            *reinterpret_cast<__half2*>(&w2s[h][p*2]) = __floats2half2_rn(f.x, f.y);
        }
        __syncthreads();
        mma_chunk(A, h1s, w2s, lane, wm, wn);
        __syncthreads();
    }

    const int g = lane >> 2, cp2 = (lane & 3) * 2;
    #pragma unroll
    for (int mt = 0; mt < 2; mt++) {
        int r0 = n0 + wm*32 + mt*16 + g, r1 = r0 + 8;
        #pragma unroll
        for (int nt = 0; nt < 8; nt++) {
            int c0 = wn*64 + nt*8 + cp2;
            float b0 = bf1[cb + c0], b1 = bf1[cb + c0 + 1];
            *reinterpret_cast<__half2*>(&g_y1h[r0][cb + c0]) =
                __floats2half2_rn(fmaxf(A.a[mt][nt][0] + b0, 0.f), fmaxf(A.a[mt][nt][1] + b1, 0.f));
            *reinterpret_cast<__half2*>(&g_y1h[r1][cb + c0]) =
                __floats2half2_rn(fmaxf(A.a[mt][nt][2] + b0, 0.f), fmaxf(A.a[mt][nt][3] + b1, 0.f));
        }
    }
}

// ---- K9: fused = y1h @ Wf2 + bf2, tensor-core --------------------------------------
__global__ void __launch_bounds__(256) k_fuse2m(const float* __restrict__ Wf2,
                                                const float* __restrict__ bf2,
                                                float* __restrict__ outf) {
    extern __shared__ char smraw[];
    MRow* h1s = (MRow*)smraw;
    MRow* w2s = (MRow*)(smraw + 128*136*sizeof(__half));
    const int n0 = blockIdx.x * 128;
    const int tid = threadIdx.x, lane = tid & 31, warp = tid >> 5;
    const int wm = warp & 3, wn = warp >> 2;

    Acc A; acc_zero(A);
    for (int kk = 0; kk < 2; kk++) {
        #pragma unroll
        for (int c = 0; c < 8; c++) {
            int e = tid + c*256;
            int r = e >> 4, u = e & 15;
            *reinterpret_cast<uint4*>(&h1s[r][u*8]) =
                *reinterpret_cast<const uint4*>(&g_y1h[n0 + r][kk*128 + u*8]);
        }
        #pragma unroll
        for (int c = 0; c < 32; c++) {
            int e = tid + c*256;
            int h = e >> 6, p = e & 63;
            float2 f = *reinterpret_cast<const float2*>(&Wf2[((size_t)(kk*128 + h))*FOUT + p*2]);
            *reinterpret_cast<__half2*>(&w2s[h][p*2]) = __floats2half2_rn(f.x, f.y);
        }
        __syncthreads();
        mma_chunk(A, h1s, w2s, lane, wm, wn);
        __syncthreads();
    }

    const int g = lane >> 2, cp2 = (lane & 3) * 2;
    #pragma unroll
    for (int mt = 0; mt < 2; mt++) {
        int r0 = n0 + wm*32 + mt*16 + g, r1 = r0 + 8;
        #pragma unroll
        for (int nt = 0; nt < 8; nt++) {
            int c0 = wn*64 + nt*8 + cp2;
            float b0 = bf2[c0], b1 = bf2[c0 + 1];
            *reinterpret_cast<float2*>(&outf[(size_t)r0*FOUT + c0]) =
                make_float2(A.a[mt][nt][0] + b0, A.a[mt][nt][1] + b1);
            *reinterpret_cast<float2*>(&outf[(size_t)r1*FOUT + c0]) =
                make_float2(A.a[mt][nt][2] + b0, A.a[mt][nt][3] + b1);
        }
    }
}

// ---- launch ------------------------------------------------------------------------
extern "C" void kernel_launch(void* const* d_in, const int* in_sizes, int n_in,
                              void* d_out, int out_size) {
    const int*   adj = (const int*)  d_in[0];
    const float* W1  = (const float*)d_in[1];
    const float* b1  = (const float*)d_in[2];
    const float* W2  = (const float*)d_in[3];
    const float* b2  = (const float*)d_in[4];
    const float* Wa1 = (const float*)d_in[5];
    const float* ba1 = (const float*)d_in[6];
    const float* Wa2 = (const float*)d_in[7];
    const float* ba2 = (const float*)d_in[8];
    const float* Wf1 = (const float*)d_in[9];
    const float* bf1 = (const float*)d_in[10];
    const float* Wf2 = (const float*)d_in[11];
    const float* bf2 = (const float*)d_in[12];

    float* out       = (float*)d_out;
    float* out_fused = out;                                   // (N, F_OUT) — base 16B aligned
    float* out_attn  = out + (size_t)NN * FOUT;               // (V,)
    float* out_h     = out + (size_t)NN * FOUT + VV;          // (V, N, H) — only 4B aligned

    static int configured = 0;
    if (!configured) {
        cudaFuncSetAttribute(k_gemm,   cudaFuncAttributeMaxDynamicSharedMemorySize, GEMM_SMEM);
        cudaFuncSetAttribute(k_w2m,    cudaFuncAttributeMaxDynamicSharedMemorySize, MMA_SMEM);
        cudaFuncSetAttribute(k_fuse1m, cudaFuncAttributeMaxDynamicSharedMemorySize, MMA_SMEM);
        cudaFuncSetAttribute(k_fuse2m, cudaFuncAttributeMaxDynamicSharedMemorySize, MMA_SMEM);
        configured = 1;
    }

    k_pack<<<dim3(NN, VV), 256>>>(adj, W1);
    k_gemm<<<dim3(NN/128, VV, KSPLIT), 256, GEMM_SMEM>>>(0);
    k_red<<<dim3(NN/128, VV), 256>>>(b1, nullptr, 1.0f/SCALE1, 0);
    k_w2m<<<dim3(NN/128, VV), 256, MMA_SMEM>>>(W2);
    k_gemm<<<dim3(NN/128, VV, KSPLIT), 256, GEMM_SMEM>>>(0);
    k_red<<<dim3(NN/128, VV), 256>>>(b2, out_h, 1.0f/SCALE2, 1);
    k_part<<<dim3(NPART, VV), 128>>>(out_h);
    k_summ_attn<<<1, 128>>>(Wa1, ba1, Wa2, ba2, out_attn);
    k_fuse1m<<<dim3(NN/128, 2), 256, MMA_SMEM>>>(out_h, Wf1, bf1);
    k_fuse2m<<<NN/128, 256, MMA_SMEM>>>(Wf2, bf2, out_fused);
}

// round 14
// speedup vs baseline: 1.2252x; 1.0757x over previous
#include <cuda_runtime.h>
#include <cuda_fp16.h>
#include <stdint.h>

#define VV 3
#define NN 8192
#define HH 128
#define ADIM 64
#define FOUT 128
#define WORDS 256
#define SCALE1 256.0f
#define SCALE2 1024.0f
#define KSPLIT 3
#define NPART 64

static __device__ uint32_t g_packed[VV][NN][WORDS];              // word 4c+k, bit l <-> col 128c+4l+k
static __device__ float    g_dinv[VV][NN];                       // natural order
static __device__ float    g_dinvp[VV][NN];                      // permuted order
static __device__ __align__(16) __half g_B16[VV][NN][HH];        // B operand, PERMUTED rows
static __device__ __align__(16) __half g_h1[VV][NN][HH];         // fp16 h1, PERMUTED rows
static __device__ __align__(16) float  g_partial[KSPLIT][VV][NN][HH];  // split-K partials (37.7 MB)
static __device__ __align__(16) __half g_y1h[NN][2*HH];          // fusion hidden, fp16
static __device__ float    g_part[VV][NPART][HH];
static __device__ float    g_attn[VV];

__device__ __forceinline__ int perm_r(int m) {
    return ((m >> 7) << 7) | ((m & 3) << 5) | (((m >> 2) & 15) << 1) | ((m >> 6) & 1);
}

// ---- K1: pack bits (permuted word order) + degree + B16 = dinv*W1*SCALE1 ----------
__global__ void __launch_bounds__(256) k_pack(const int* __restrict__ adj,
                                              const float* __restrict__ W1) {
    const int row = blockIdx.x, v = blockIdx.y;
    const int tid = threadIdx.x, lane = tid & 31, warp = tid >> 5;
    const int4* __restrict__ arow =
        reinterpret_cast<const int4*>(adj + ((size_t)v*NN + row)*(size_t)NN);
    int cnt = 0;
    #pragma unroll
    for (int c = warp; c < 64; c += 8) {
        int4 x = __ldg(&arow[c*32 + lane]);
        int base = c*128 + lane*4;
        bool b0 = (x.x != 0) || (base + 0 == row);
        bool b1 = (x.y != 0) || (base + 1 == row);
        bool b2 = (x.z != 0) || (base + 2 == row);
        bool b3 = (x.w != 0) || (base + 3 == row);
        unsigned m0 = __ballot_sync(0xffffffffu, b0);
        unsigned m1 = __ballot_sync(0xffffffffu, b1);
        unsigned m2 = __ballot_sync(0xffffffffu, b2);
        unsigned m3 = __ballot_sync(0xffffffffu, b3);
        if (lane == 0)
            *reinterpret_cast<uint4*>(&g_packed[v][row][4*c]) = make_uint4(m0, m1, m2, m3);
        cnt += (int)b0 + (int)b1 + (int)b2 + (int)b3;
    }
    #pragma unroll
    for (int o = 16; o; o >>= 1) cnt += __shfl_xor_sync(0xffffffffu, cnt, o);
    __shared__ int sc[8];
    __shared__ float sdinv;
    if (lane == 0) sc[warp] = cnt;
    __syncthreads();
    if (tid == 0) {
        int d = 0;
        #pragma unroll
        for (int i = 0; i < 8; i++) d += sc[i];
        float di = rsqrtf((float)d);
        sdinv = di;
        g_dinv[v][row] = di;
        g_dinvp[v][perm_r(row)] = di;
    }
    __syncthreads();
    if (tid < HH) {
        int rp = perm_r(row);
        g_B16[v][rp][tid] = __float2half(W1[((size_t)v*NN + row)*HH + tid] * sdinv * SCALE1);
    }
}

// ---- mma helpers -------------------------------------------------------------------
__device__ __forceinline__ uint32_t smem_u32(const void* p) {
    return (uint32_t)__cvta_generic_to_shared(p);
}
__device__ __forceinline__ void ldsm_x4(uint32_t& r0, uint32_t& r1, uint32_t& r2, uint32_t& r3, uint32_t a) {
    asm volatile("ldmatrix.sync.aligned.m8n8.x4.shared.b16 {%0,%1,%2,%3}, [%4];"
                 : "=r"(r0), "=r"(r1), "=r"(r2), "=r"(r3) : "r"(a));
}
__device__ __forceinline__ void ldsm_x4_t(uint32_t& r0, uint32_t& r1, uint32_t& r2, uint32_t& r3, uint32_t a) {
    asm volatile("ldmatrix.sync.aligned.m8n8.x4.trans.shared.b16 {%0,%1,%2,%3}, [%4];"
                 : "=r"(r0), "=r"(r1), "=r"(r2), "=r"(r3) : "r"(a));
}
__device__ __forceinline__ void mma16816(float* c, const uint32_t* a, const uint32_t* b) {
    asm volatile("mma.sync.aligned.m16n8k16.row.col.f32.f16.f16.f32 "
                 "{%0,%1,%2,%3}, {%4,%5,%6,%7}, {%8,%9}, {%0,%1,%2,%3};"
                 : "+f"(c[0]), "+f"(c[1]), "+f"(c[2]), "+f"(c[3])
                 : "r"(a[0]), "r"(a[1]), "r"(a[2]), "r"(a[3]), "r"(b[0]), "r"(b[1]));
}
#define CP_ASYNC16(dst, src) \
    asm volatile("cp.async.cg.shared.global [%0], [%1], 16;" :: "r"(dst), "l"(src))
#define CP_COMMIT()   asm volatile("cp.async.commit_group;")
#define CP_WAIT(n)    asm volatile("cp.async.wait_group %0;" :: "n"(n))

// ---- shared mma-tile body (used by w2m/fuse kernels) -------------------------------
typedef __half MRow[136];
struct Acc { float a[2][8][4]; };
__device__ __forceinline__ void mma_chunk(Acc& A, const MRow* h1s, const MRow* w2s,
                                          int lane, int wm, int wn) {
    #pragma unroll
    for (int ks = 0; ks < 8; ks++) {
        const int k = ks * 16;
        uint32_t a[2][4];
        #pragma unroll
        for (int mt = 0; mt < 2; mt++) {
            const __half* p = &h1s[wm*32 + mt*16 + (lane & 7) + ((lane & 8) ? 8 : 0)]
                                  [k + ((lane & 16) ? 8 : 0)];
            ldsm_x4(a[mt][0], a[mt][1], a[mt][2], a[mt][3], smem_u32(p));
        }
        uint32_t b[8][2];
        #pragma unroll
        for (int nt2 = 0; nt2 < 4; nt2++) {
            int krow = k + (lane & 7) + ((lane & 8) ? 8 : 0);
            int ncol = wn*64 + nt2*16 + ((lane & 16) ? 8 : 0);
            uint32_t r0, r1, r2, r3;
            ldsm_x4_t(r0, r1, r2, r3, smem_u32(&w2s[krow][ncol]));
            b[nt2*2][0] = r0; b[nt2*2][1] = r1;
            b[nt2*2+1][0] = r2; b[nt2*2+1][1] = r3;
        }
        #pragma unroll
        for (int mt = 0; mt < 2; mt++)
            #pragma unroll
            for (int nt = 0; nt < 8; nt++)
                mma16816(A.a[mt][nt], a[mt], b[nt]);
    }
}
__device__ __forceinline__ void acc_zero(Acc& A) {
    #pragma unroll
    for (int a = 0; a < 2; a++)
        #pragma unroll
        for (int b = 0; b < 8; b++)
            #pragma unroll
            for (int c = 0; c < 4; c++) A.a[a][b][c] = 0.f;
}

// bit pair (q, q+16) of w -> fp16 {0,1} pair
__device__ __forceinline__ uint32_t bitcvt(uint32_t w, int q, __half2 c1024) {
    uint32_t t = ((w >> q) & 0x00010001u) | 0x64006400u;
    __half2 h = __hsub2(*(__half2*)&t, c1024);
    return *(uint32_t*)&h;
}

// ---- K2/K4: masked GEMM, split-K, K-chunk=128, 4x2 tiling, reg A frags,
// ----        3-stage B ring with ONE barrier per chunk ------------------------------
#define GEMM_SMEM (3*128*136*(int)sizeof(__half))   // 3x B buffers = 104448
__global__ void __launch_bounds__(256, 2) k_gemm(int dummy) {
    extern __shared__ char smraw[];
    const int v  = blockIdx.y;
    const int n0 = blockIdx.x * 128;
    const int sl = blockIdx.z;
    const int c0 = (sl * 64) / KSPLIT;
    const int c1 = ((sl + 1) * 64) / KSPLIT;
    const int tid = threadIdx.x;
    const int lane = tid & 31, warp = tid >> 5;
    const int wm = warp & 3, wn = warp >> 2;
    const int g = lane >> 2, l3 = lane & 3;
    const __half2 c1024 = __half2half2(__ushort_as_half(0x6400));

    Acc A; acc_zero(A);
    const uint4* rowp[2][2];
    #pragma unroll
    for (int mt = 0; mt < 2; mt++)
        #pragma unroll
        for (int h = 0; h < 2; h++)
            rowp[mt][h] = reinterpret_cast<const uint4*>(
                g_packed[v][n0 + wm*32 + mt*16 + h*8 + g]);

    auto loadB = [&](int chunk, int buf) {
        MRow* Bs = (MRow*)(smraw + (size_t)buf*128*136*sizeof(__half));
        #pragma unroll
        for (int c = 0; c < 8; c++) {
            int ch = tid + c*256;
            int kr = ch >> 4, hc = (ch & 15) * 8;
            CP_ASYNC16(smem_u32(&Bs[kr][hc]), &g_B16[v][chunk*128 + kr][hc]);
        }
        CP_COMMIT();
    };

    loadB(c0, 0);
    for (int i = c0; i < c1; i++) {
        const int bi = (i - c0) % 3;
        MRow* Bcur = (MRow*)(smraw + (size_t)bi*128*136*sizeof(__half));
        uint32_t W[2][2][4];
        #pragma unroll
        for (int mt = 0; mt < 2; mt++)
            #pragma unroll
            for (int h = 0; h < 2; h++) {
                uint4 u = __ldg(&rowp[mt][h][i]);
                W[mt][h][0] = u.x; W[mt][h][1] = u.y; W[mt][h][2] = u.z; W[mt][h][3] = u.w;
            }
        if (i + 1 < c1) { loadB(i + 1, (i + 1 - c0) % 3); CP_WAIT(1); }
        else            { CP_WAIT(0); }
        __syncthreads();   // single barrier: publishes chunk i's B; also fences ring reuse

        #pragma unroll
        for (int ks = 0; ks < 8; ks++) {
            const int k = ks * 16;
            const int j  = ks >> 1;
            const int q0 = (ks & 1) * 8 + l3;
            uint32_t a[2][4];
            #pragma unroll
            for (int mt = 0; mt < 2; mt++) {
                a[mt][0] = bitcvt(W[mt][0][j], q0,     c1024);
                a[mt][1] = bitcvt(W[mt][1][j], q0,     c1024);
                a[mt][2] = bitcvt(W[mt][0][j], q0 + 4, c1024);
                a[mt][3] = bitcvt(W[mt][1][j], q0 + 4, c1024);
            }
            uint32_t b[8][2];
            #pragma unroll
            for (int nt2 = 0; nt2 < 4; nt2++) {
                int krow = k + (lane & 7) + ((lane & 8) ? 8 : 0);
                int ncol = wn*64 + nt2*16 + ((lane & 16) ? 8 : 0);
                uint32_t r0, r1, r2, r3;
                ldsm_x4_t(r0, r1, r2, r3, smem_u32(&Bcur[krow][ncol]));
                b[nt2*2][0] = r0; b[nt2*2][1] = r1;
                b[nt2*2+1][0] = r2; b[nt2*2+1][1] = r3;
            }
            #pragma unroll
            for (int mt = 0; mt < 2; mt++)
                #pragma unroll
                for (int nt = 0; nt < 8; nt++)
                    mma16816(A.a[mt][nt], a[mt], b[nt]);
        }
        // no trailing barrier: 3-stage ring; next iteration's barrier fences reuse
    }

    const int cp2 = l3 * 2;
    float* pp = &g_partial[sl][v][0][0];
    #pragma unroll
    for (int mt = 0; mt < 2; mt++) {
        int nl0 = n0 + wm*32 + mt*16 + g, nl1 = nl0 + 8;
        #pragma unroll
        for (int nt = 0; nt < 8; nt++) {
            int cc = wn*64 + nt*8 + cp2;
            *reinterpret_cast<float2*>(&pp[(size_t)nl0*HH + cc]) =
                make_float2(A.a[mt][nt][0], A.a[mt][nt][1]);
            *reinterpret_cast<float2*>(&pp[(size_t)nl1*HH + cc]) =
                make_float2(A.a[mt][nt][2], A.a[mt][nt][3]);
        }
    }
    (void)dummy;
}

// ---- K3/K5: reduce split-K partials + epilogue -------------------------------------
__global__ void __launch_bounds__(256) k_red(const float* __restrict__ bias,
                                             float* __restrict__ outp,
                                             float invscale, int mode) {
    const int v = blockIdx.y, n0 = blockIdx.x * 128;
    const int tid = threadIdx.x;
    const int row = n0 + (tid >> 1);
    const int cb  = (tid & 1) * 64;
    const float dsc = g_dinv[v][row] * invscale;
    const size_t off = ((size_t)v*NN + row)*HH + cb;
    const size_t sstr = (size_t)VV*NN*HH;
    const float* p0 = &g_partial[0][0][0][0] + off;
    const int rp = perm_r(row);
    float* orow = (mode == 1) ? (outp + ((size_t)v*NN + row)*HH) : nullptr;
    #pragma unroll
    for (int j = 0; j < 64; j += 4) {
        float4 s = *reinterpret_cast<const float4*>(p0 + j);
        #pragma unroll
        for (int sl = 1; sl < KSPLIT; sl++) {
            float4 t = *reinterpret_cast<const float4*>(p0 + sl*sstr + j);
            s.x += t.x; s.y += t.y; s.z += t.z; s.w += t.w;
        }
        int col = cb + j;
        float r0 = fmaxf(fmaf(dsc, s.x, bias[v*HH + col    ]), 0.f);
        float r1 = fmaxf(fmaf(dsc, s.y, bias[v*HH + col + 1]), 0.f);
        float r2 = fmaxf(fmaf(dsc, s.z, bias[v*HH + col + 2]), 0.f);
        float r3 = fmaxf(fmaf(dsc, s.w, bias[v*HH + col + 3]), 0.f);
        if (mode == 0) {
            *reinterpret_cast<__half2*>(&g_h1[v][rp][col])     = __floats2half2_rn(r0, r1);
            *reinterpret_cast<__half2*>(&g_h1[v][rp][col + 2]) = __floats2half2_rn(r2, r3);
        } else {
            orow[col]     = r0;   // d_out region only 4B-aligned -> scalar stores
            orow[col + 1] = r1;
            orow[col + 2] = r2;
            orow[col + 3] = r3;
        }
    }
}

// ---- K4b: B16 = dinvp * SCALE2 * (h1 @ W2), permuted row space ---------------------
#define MMA_SMEM (2*128*136*(int)sizeof(__half))
__global__ void __launch_bounds__(256) k_w2m(const float* __restrict__ W2) {
    extern __shared__ char smraw[];
    MRow* h1s = (MRow*)smraw;
    MRow* w2s = (MRow*)(smraw + 128*136*sizeof(__half));
    const int v = blockIdx.y, n0 = blockIdx.x * 128;
    const int tid = threadIdx.x, lane = tid & 31, warp = tid >> 5;
    const int wm = warp & 3, wn = warp >> 2;

    #pragma unroll
    for (int c = 0; c < 8; c++) {
        int e = tid + c*256;
        int r = e >> 4, u = e & 15;
        *reinterpret_cast<uint4*>(&h1s[r][u*8]) =
            *reinterpret_cast<const uint4*>(&g_h1[v][n0 + r][u*8]);
    }
    #pragma unroll
    for (int c = 0; c < 32; c++) {
        int e = tid + c*256;
        int h = e >> 6, p = e & 63;
        float2 f = *reinterpret_cast<const float2*>(&W2[((size_t)v*HH + h)*HH + p*2]);
        *reinterpret_cast<__half2*>(&w2s[h][p*2]) = __floats2half2_rn(f.x, f.y);
    }
    __syncthreads();

    Acc A; acc_zero(A);
    mma_chunk(A, h1s, w2s, lane, wm, wn);

    const int g = lane >> 2, cp2 = (lane & 3) * 2;
    #pragma unroll
    for (int mt = 0; mt < 2; mt++) {
        int r0 = n0 + wm*32 + mt*16 + g, r1 = r0 + 8;
        float d0 = g_dinvp[v][r0] * SCALE2;
        float d1 = g_dinvp[v][r1] * SCALE2;
        #pragma unroll
        for (int nt = 0; nt < 8; nt++) {
            int c0 = wn*64 + nt*8 + cp2;
            *reinterpret_cast<__half2*>(&g_B16[v][r0][c0]) =
                __floats2half2_rn(A.a[mt][nt][0]*d0, A.a[mt][nt][1]*d0);
            *reinterpret_cast<__half2*>(&g_B16[v][r1][c0]) =
                __floats2half2_rn(A.a[mt][nt][2]*d1, A.a[mt][nt][3]*d1);
        }
    }
}

// ---- K6: mean-pool partials --------------------------------------------------------
__global__ void __launch_bounds__(128) k_part(const float* __restrict__ hmat) {
    const int p = blockIdx.x, v = blockIdx.y, h = threadIdx.x;
    float s = 0.f;
    const int span = NN / NPART;
    for (int n = p*span; n < (p+1)*span; n++)
        s += hmat[((size_t)v*NN + n)*HH + h];
    g_part[v][p][h] = s;
}

// ---- K7: summaries + attention softmax ---------------------------------------------
__global__ void __launch_bounds__(128) k_summ_attn(const float* __restrict__ Wa1,
                                                   const float* __restrict__ ba1,
                                                   const float* __restrict__ Wa2,
                                                   const float* __restrict__ ba2,
                                                   float* __restrict__ outattn) {
    __shared__ float summ[VV][HH];
    __shared__ float s1[ADIM];
    __shared__ float sc[VV];
    const int tid = threadIdx.x;
    #pragma unroll
    for (int v = 0; v < VV; v++) {
        float s = 0.f;
        #pragma unroll
        for (int p = 0; p < NPART; p++) s += g_part[v][p][tid];
        summ[v][tid] = s * (1.0f / (float)NN);
    }
    __syncthreads();
    for (int v = 0; v < VV; v++) {
        if (tid < ADIM) {
            float a = ba1[tid];
            for (int hh = 0; hh < HH; hh++) a = fmaf(summ[v][hh], Wa1[hh*ADIM + tid], a);
            s1[tid] = tanhf(a);
        }
        __syncthreads();
        if (tid == 0) {
            float sv = ba2[0];
            for (int j = 0; j < ADIM; j++) sv = fmaf(s1[j], Wa2[j], sv);
            sc[v] = sv;
        }
        __syncthreads();
    }
    if (tid == 0) {
        float m = fmaxf(sc[0], fmaxf(sc[1], sc[2]));
        float e0 = expf(sc[0]-m), e1 = expf(sc[1]-m), e2 = expf(sc[2]-m);
        float inv = 1.f / (e0 + e1 + e2);
        g_attn[0] = e0*inv; g_attn[1] = e1*inv; g_attn[2] = e2*inv;
        outattn[0] = e0*inv; outattn[1] = e1*inv; outattn[2] = e2*inv;
    }
}

// ---- K8: y1h = fp16(relu([h*attn] @ Wf1 + bf1)), tensor-core -----------------------
__global__ void __launch_bounds__(256) k_fuse1m(const float* __restrict__ hsrc,
                                                const float* __restrict__ Wf1,
                                                const float* __restrict__ bf1) {
    extern __shared__ char smraw[];
    MRow* h1s = (MRow*)smraw;
    MRow* w2s = (MRow*)(smraw + 128*136*sizeof(__half));
    const int n0 = blockIdx.x * 128;
    const int cb = blockIdx.y * 128;
    const int tid = threadIdx.x, lane = tid & 31, warp = tid >> 5;
    const int wm = warp & 3, wn = warp >> 2;

    Acc A; acc_zero(A);
    for (int v = 0; v < VV; v++) {
        float av = g_attn[v];
        const float* hs = hsrc + (size_t)v*NN*HH + (size_t)n0*HH;
        for (int idx = tid; idx < 128*128; idx += 256) {
            int r = idx >> 7, c = idx & 127;
            h1s[r][c] = __float2half(hs[(size_t)r*HH + c] * av);
        }
        #pragma unroll
        for (int c = 0; c < 32; c++) {
            int e = tid + c*256;
            int h = e >> 6, p = e & 63;
            float2 f = *reinterpret_cast<const float2*>(&Wf1[((size_t)(v*128 + h))*(2*HH) + cb + p*2]);
            *reinterpret_cast<__half2*>(&w2s[h][p*2]) = __floats2half2_rn(f.x, f.y);
        }
        __syncthreads();
        mma_chunk(A, h1s, w2s, lane, wm, wn);
        __syncthreads();
    }

    const int g = lane >> 2, cp2 = (lane & 3) * 2;
    #pragma unroll
    for (int mt = 0; mt < 2; mt++) {
        int r0 = n0 + wm*32 + mt*16 + g, r1 = r0 + 8;
        #pragma unroll
        for (int nt = 0; nt < 8; nt++) {
            int c0 = wn*64 + nt*8 + cp2;
            float b0 = bf1[cb + c0], b1 = bf1[cb + c0 + 1];
            *reinterpret_cast<__half2*>(&g_y1h[r0][cb + c0]) =
                __floats2half2_rn(fmaxf(A.a[mt][nt][0] + b0, 0.f), fmaxf(A.a[mt][nt][1] + b1, 0.f));
            *reinterpret_cast<__half2*>(&g_y1h[r1][cb + c0]) =
                __floats2half2_rn(fmaxf(A.a[mt][nt][2] + b0, 0.f), fmaxf(A.a[mt][nt][3] + b1, 0.f));
        }
    }
}

// ---- K9: fused = y1h @ Wf2 + bf2, tensor-core --------------------------------------
__global__ void __launch_bounds__(256) k_fuse2m(const float* __restrict__ Wf2,
                                                const float* __restrict__ bf2,
                                                float* __restrict__ outf) {
    extern __shared__ char smraw[];
    MRow* h1s = (MRow*)smraw;
    MRow* w2s = (MRow*)(smraw + 128*136*sizeof(__half));
    const int n0 = blockIdx.x * 128;
    const int tid = threadIdx.x, lane = tid & 31, warp = tid >> 5;
    const int wm = warp & 3, wn = warp >> 2;

    Acc A; acc_zero(A);
    for (int kk = 0; kk < 2; kk++) {
        #pragma unroll
        for (int c = 0; c < 8; c++) {
            int e = tid + c*256;
            int r = e >> 4, u = e & 15;
            *reinterpret_cast<uint4*>(&h1s[r][u*8]) =
                *reinterpret_cast<const uint4*>(&g_y1h[n0 + r][kk*128 + u*8]);
        }
        #pragma unroll
        for (int c = 0; c < 32; c++) {
            int e = tid + c*256;
            int h = e >> 6, p = e & 63;
            float2 f = *reinterpret_cast<const float2*>(&Wf2[((size_t)(kk*128 + h))*FOUT + p*2]);
            *reinterpret_cast<__half2*>(&w2s[h][p*2]) = __floats2half2_rn(f.x, f.y);
        }
        __syncthreads();
        mma_chunk(A, h1s, w2s, lane, wm, wn);
        __syncthreads();
    }

    const int g = lane >> 2, cp2 = (lane & 3) * 2;
    #pragma unroll
    for (int mt = 0; mt < 2; mt++) {
        int r0 = n0 + wm*32 + mt*16 + g, r1 = r0 + 8;
        #pragma unroll
        for (int nt = 0; nt < 8; nt++) {
            int c0 = wn*64 + nt*8 + cp2;
            float b0 = bf2[c0], b1 = bf2[c0 + 1];
            *reinterpret_cast<float2*>(&outf[(size_t)r0*FOUT + c0]) =
                make_float2(A.a[mt][nt][0] + b0, A.a[mt][nt][1] + b1);
            *reinterpret_cast<float2*>(&outf[(size_t)r1*FOUT + c0]) =
                make_float2(A.a[mt][nt][2] + b0, A.a[mt][nt][3] + b1);
        }
    }
}

// ---- launch ------------------------------------------------------------------------
extern "C" void kernel_launch(void* const* d_in, const int* in_sizes, int n_in,
                              void* d_out, int out_size) {
    const int*   adj = (const int*)  d_in[0];
    const float* W1  = (const float*)d_in[1];
    const float* b1  = (const float*)d_in[2];
    const float* W2  = (const float*)d_in[3];
    const float* b2  = (const float*)d_in[4];
    const float* Wa1 = (const float*)d_in[5];
    const float* ba1 = (const float*)d_in[6];
    const float* Wa2 = (const float*)d_in[7];
    const float* ba2 = (const float*)d_in[8];
    const float* Wf1 = (const float*)d_in[9];
    const float* bf1 = (const float*)d_in[10];
    const float* Wf2 = (const float*)d_in[11];
    const float* bf2 = (const float*)d_in[12];

    float* out       = (float*)d_out;
    float* out_fused = out;                                   // (N, F_OUT) — base 16B aligned
    float* out_attn  = out + (size_t)NN * FOUT;               // (V,)
    float* out_h     = out + (size_t)NN * FOUT + VV;          // (V, N, H) — only 4B aligned

    static int configured = 0;
    if (!configured) {
        cudaFuncSetAttribute(k_gemm,   cudaFuncAttributeMaxDynamicSharedMemorySize, GEMM_SMEM);
        cudaFuncSetAttribute(k_w2m,    cudaFuncAttributeMaxDynamicSharedMemorySize, MMA_SMEM);
        cudaFuncSetAttribute(k_fuse1m, cudaFuncAttributeMaxDynamicSharedMemorySize, MMA_SMEM);
        cudaFuncSetAttribute(k_fuse2m, cudaFuncAttributeMaxDynamicSharedMemorySize, MMA_SMEM);
        configured = 1;
    }

    k_pack<<<dim3(NN, VV), 256>>>(adj, W1);
    k_gemm<<<dim3(NN/128, VV, KSPLIT), 256, GEMM_SMEM>>>(0);
    k_red<<<dim3(NN/128, VV), 256>>>(b1, nullptr, 1.0f/SCALE1, 0);
    k_w2m<<<dim3(NN/128, VV), 256, MMA_SMEM>>>(W2);
    k_gemm<<<dim3(NN/128, VV, KSPLIT), 256, GEMM_SMEM>>>(0);
    k_red<<<dim3(NN/128, VV), 256>>>(b2, out_h, 1.0f/SCALE2, 1);
    k_part<<<dim3(NPART, VV), 128>>>(out_h);
    k_summ_attn<<<1, 128>>>(Wa1, ba1, Wa2, ba2, out_attn);
    k_fuse1m<<<dim3(NN/128, 2), 256, MMA_SMEM>>>(out_h, Wf1, bf1);
    k_fuse2m<<<NN/128, 256, MMA_SMEM>>>(Wf2, bf2, out_fused);
}

// round 15
// speedup vs baseline: 1.2542x; 1.0236x over previous
#include <cuda_runtime.h>
#include <cuda_fp16.h>
#include <stdint.h>

#define VV 3
#define NN 8192
#define HH 128
#define ADIM 64
#define FOUT 128
#define WORDS 256
#define SCALE1 256.0f
#define SCALE2 1024.0f
#define KSPLIT 3
#define NPART 64

static __device__ uint32_t g_packed[VV][NN][WORDS];              // word 4c+k, bit l <-> col 128c+4l+k
static __device__ float    g_dinv[VV][NN];                       // natural order
static __device__ float    g_dinvp[VV][NN];                      // permuted order
static __device__ __align__(16) __half g_B16[VV][NN][HH];        // B operand, PERMUTED rows
static __device__ __align__(16) __half g_h1[VV][NN][HH];         // fp16 h1, PERMUTED rows
static __device__ __align__(16) __half g_h16[VV][NN][HH];        // fp16 mirror of h (natural rows)
static __device__ __align__(16) float  g_partial[KSPLIT][VV][NN][HH];  // split-K partials (37.7 MB)
static __device__ __align__(16) __half g_y1h[NN][2*HH];          // fusion hidden, fp16
static __device__ float    g_part[VV][NPART][HH];
static __device__ float    g_attn[VV];

__device__ __forceinline__ int perm_r(int m) {
    return ((m >> 7) << 7) | ((m & 3) << 5) | (((m >> 2) & 15) << 1) | ((m >> 6) & 1);
}

// ---- K1: pack bits (permuted word order) + degree + B16 = dinv*W1*SCALE1 ----------
__global__ void __launch_bounds__(256) k_pack(const int* __restrict__ adj,
                                              const float* __restrict__ W1) {
    const int row = blockIdx.x, v = blockIdx.y;
    const int tid = threadIdx.x, lane = tid & 31, warp = tid >> 5;
    const int4* __restrict__ arow =
        reinterpret_cast<const int4*>(adj + ((size_t)v*NN + row)*(size_t)NN);
    int cnt = 0;
    #pragma unroll
    for (int c = warp; c < 64; c += 8) {
        int4 x = __ldg(&arow[c*32 + lane]);
        int base = c*128 + lane*4;
        bool b0 = (x.x != 0) || (base + 0 == row);
        bool b1 = (x.y != 0) || (base + 1 == row);
        bool b2 = (x.z != 0) || (base + 2 == row);
        bool b3 = (x.w != 0) || (base + 3 == row);
        unsigned m0 = __ballot_sync(0xffffffffu, b0);
        unsigned m1 = __ballot_sync(0xffffffffu, b1);
        unsigned m2 = __ballot_sync(0xffffffffu, b2);
        unsigned m3 = __ballot_sync(0xffffffffu, b3);
        if (lane == 0)
            *reinterpret_cast<uint4*>(&g_packed[v][row][4*c]) = make_uint4(m0, m1, m2, m3);
        cnt += (int)b0 + (int)b1 + (int)b2 + (int)b3;
    }
    #pragma unroll
    for (int o = 16; o; o >>= 1) cnt += __shfl_xor_sync(0xffffffffu, cnt, o);
    __shared__ int sc[8];
    __shared__ float sdinv;
    if (lane == 0) sc[warp] = cnt;
    __syncthreads();
    if (tid == 0) {
        int d = 0;
        #pragma unroll
        for (int i = 0; i < 8; i++) d += sc[i];
        float di = rsqrtf((float)d);
        sdinv = di;
        g_dinv[v][row] = di;
        g_dinvp[v][perm_r(row)] = di;
    }
    __syncthreads();
    if (tid < HH) {
        int rp = perm_r(row);
        g_B16[v][rp][tid] = __float2half(W1[((size_t)v*NN + row)*HH + tid] * sdinv * SCALE1);
    }
}

// ---- mma helpers -------------------------------------------------------------------
__device__ __forceinline__ uint32_t smem_u32(const void* p) {
    return (uint32_t)__cvta_generic_to_shared(p);
}
__device__ __forceinline__ void ldsm_x4(uint32_t& r0, uint32_t& r1, uint32_t& r2, uint32_t& r3, uint32_t a) {
    asm volatile("ldmatrix.sync.aligned.m8n8.x4.shared.b16 {%0,%1,%2,%3}, [%4];"
                 : "=r"(r0), "=r"(r1), "=r"(r2), "=r"(r3) : "r"(a));
}
__device__ __forceinline__ void ldsm_x4_t(uint32_t& r0, uint32_t& r1, uint32_t& r2, uint32_t& r3, uint32_t a) {
    asm volatile("ldmatrix.sync.aligned.m8n8.x4.trans.shared.b16 {%0,%1,%2,%3}, [%4];"
                 : "=r"(r0), "=r"(r1), "=r"(r2), "=r"(r3) : "r"(a));
}
__device__ __forceinline__ void mma16816(float* c, const uint32_t* a, const uint32_t* b) {
    asm volatile("mma.sync.aligned.m16n8k16.row.col.f32.f16.f16.f32 "
                 "{%0,%1,%2,%3}, {%4,%5,%6,%7}, {%8,%9}, {%0,%1,%2,%3};"
                 : "+f"(c[0]), "+f"(c[1]), "+f"(c[2]), "+f"(c[3])
                 : "r"(a[0]), "r"(a[1]), "r"(a[2]), "r"(a[3]), "r"(b[0]), "r"(b[1]));
}
#define CP_ASYNC16(dst, src) \
    asm volatile("cp.async.cg.shared.global [%0], [%1], 16;" :: "r"(dst), "l"(src))
#define CP_COMMIT()   asm volatile("cp.async.commit_group;")
#define CP_WAIT(n)    asm volatile("cp.async.wait_group %0;" :: "n"(n))

// ---- shared mma-tile body (used by w2m/fuse kernels) -------------------------------
typedef __half MRow[136];
struct Acc { float a[2][8][4]; };
__device__ __forceinline__ void mma_chunk(Acc& A, const MRow* h1s, const MRow* w2s,
                                          int lane, int wm, int wn) {
    #pragma unroll
    for (int ks = 0; ks < 8; ks++) {
        const int k = ks * 16;
        uint32_t a[2][4];
        #pragma unroll
        for (int mt = 0; mt < 2; mt++) {
            const __half* p = &h1s[wm*32 + mt*16 + (lane & 7) + ((lane & 8) ? 8 : 0)]
                                  [k + ((lane & 16) ? 8 : 0)];
            ldsm_x4(a[mt][0], a[mt][1], a[mt][2], a[mt][3], smem_u32(p));
        }
        uint32_t b[8][2];
        #pragma unroll
        for (int nt2 = 0; nt2 < 4; nt2++) {
            int krow = k + (lane & 7) + ((lane & 8) ? 8 : 0);
            int ncol = wn*64 + nt2*16 + ((lane & 16) ? 8 : 0);
            uint32_t r0, r1, r2, r3;
            ldsm_x4_t(r0, r1, r2, r3, smem_u32(&w2s[krow][ncol]));
            b[nt2*2][0] = r0; b[nt2*2][1] = r1;
            b[nt2*2+1][0] = r2; b[nt2*2+1][1] = r3;
        }
        #pragma unroll
        for (int mt = 0; mt < 2; mt++)
            #pragma unroll
            for (int nt = 0; nt < 8; nt++)
                mma16816(A.a[mt][nt], a[mt], b[nt]);
    }
}
__device__ __forceinline__ void acc_zero(Acc& A) {
    #pragma unroll
    for (int a = 0; a < 2; a++)
        #pragma unroll
        for (int b = 0; b < 8; b++)
            #pragma unroll
            for (int c = 0; c < 4; c++) A.a[a][b][c] = 0.f;
}

// bit pair (q, q+16) of w -> fp16 {0,1} pair
__device__ __forceinline__ uint32_t bitcvt(uint32_t w, int q, __half2 c1024) {
    uint32_t t = ((w >> q) & 0x00010001u) | 0x64006400u;
    __half2 h = __hsub2(*(__half2*)&t, c1024);
    return *(uint32_t*)&h;
}

// ---- K2/K4: masked GEMM, split-K, K-chunk=128, 4x2 tiling, reg A frags,
// ----        3-stage B ring with ONE barrier per chunk ------------------------------
#define GEMM_SMEM (3*128*136*(int)sizeof(__half))   // 3x B buffers = 104448
__global__ void __launch_bounds__(256, 2) k_gemm(int dummy) {
    extern __shared__ char smraw[];
    const int v  = blockIdx.y;
    const int n0 = blockIdx.x * 128;
    const int sl = blockIdx.z;
    const int c0 = (sl * 64) / KSPLIT;
    const int c1 = ((sl + 1) * 64) / KSPLIT;
    const int tid = threadIdx.x;
    const int lane = tid & 31, warp = tid >> 5;
    const int wm = warp & 3, wn = warp >> 2;
    const int g = lane >> 2, l3 = lane & 3;
    const __half2 c1024 = __half2half2(__ushort_as_half(0x6400));

    Acc A; acc_zero(A);
    const uint4* rowp[2][2];
    #pragma unroll
    for (int mt = 0; mt < 2; mt++)
        #pragma unroll
        for (int h = 0; h < 2; h++)
            rowp[mt][h] = reinterpret_cast<const uint4*>(
                g_packed[v][n0 + wm*32 + mt*16 + h*8 + g]);

    auto loadB = [&](int chunk, int buf) {
        MRow* Bs = (MRow*)(smraw + (size_t)buf*128*136*sizeof(__half));
        #pragma unroll
        for (int c = 0; c < 8; c++) {
            int ch = tid + c*256;
            int kr = ch >> 4, hc = (ch & 15) * 8;
            CP_ASYNC16(smem_u32(&Bs[kr][hc]), &g_B16[v][chunk*128 + kr][hc]);
        }
        CP_COMMIT();
    };

    loadB(c0, 0);
    for (int i = c0; i < c1; i++) {
        const int bi = (i - c0) % 3;
        MRow* Bcur = (MRow*)(smraw + (size_t)bi*128*136*sizeof(__half));
        uint32_t W[2][2][4];
        #pragma unroll
        for (int mt = 0; mt < 2; mt++)
            #pragma unroll
            for (int h = 0; h < 2; h++) {
                uint4 u = __ldg(&rowp[mt][h][i]);
                W[mt][h][0] = u.x; W[mt][h][1] = u.y; W[mt][h][2] = u.z; W[mt][h][3] = u.w;
            }
        if (i + 1 < c1) { loadB(i + 1, (i + 1 - c0) % 3); CP_WAIT(1); }
        else            { CP_WAIT(0); }
        __syncthreads();   // single barrier: publishes chunk i's B; also fences ring reuse

        #pragma unroll
        for (int ks = 0; ks < 8; ks++) {
            const int k = ks * 16;
            const int j  = ks >> 1;
            const int q0 = (ks & 1) * 8 + l3;
            uint32_t a[2][4];
            #pragma unroll
            for (int mt = 0; mt < 2; mt++) {
                a[mt][0] = bitcvt(W[mt][0][j], q0,     c1024);
                a[mt][1] = bitcvt(W[mt][1][j], q0,     c1024);
                a[mt][2] = bitcvt(W[mt][0][j], q0 + 4, c1024);
                a[mt][3] = bitcvt(W[mt][1][j], q0 + 4, c1024);
            }
            uint32_t b[8][2];
            #pragma unroll
            for (int nt2 = 0; nt2 < 4; nt2++) {
                int krow = k + (lane & 7) + ((lane & 8) ? 8 : 0);
                int ncol = wn*64 + nt2*16 + ((lane & 16) ? 8 : 0);
                uint32_t r0, r1, r2, r3;
                ldsm_x4_t(r0, r1, r2, r3, smem_u32(&Bcur[krow][ncol]));
                b[nt2*2][0] = r0; b[nt2*2][1] = r1;
                b[nt2*2+1][0] = r2; b[nt2*2+1][1] = r3;
            }
            #pragma unroll
            for (int mt = 0; mt < 2; mt++)
                #pragma unroll
                for (int nt = 0; nt < 8; nt++)
                    mma16816(A.a[mt][nt], a[mt], b[nt]);
        }
        // no trailing barrier: 3-stage ring; next iteration's barrier fences reuse
    }

    const int cp2 = l3 * 2;
    float* pp = &g_partial[sl][v][0][0];
    #pragma unroll
    for (int mt = 0; mt < 2; mt++) {
        int nl0 = n0 + wm*32 + mt*16 + g, nl1 = nl0 + 8;
        #pragma unroll
        for (int nt = 0; nt < 8; nt++) {
            int cc = wn*64 + nt*8 + cp2;
            *reinterpret_cast<float2*>(&pp[(size_t)nl0*HH + cc]) =
                make_float2(A.a[mt][nt][0], A.a[mt][nt][1]);
            *reinterpret_cast<float2*>(&pp[(size_t)nl1*HH + cc]) =
                make_float2(A.a[mt][nt][2], A.a[mt][nt][3]);
        }
    }
    (void)dummy;
}

// ---- K3/K5: reduce split-K partials + epilogue -------------------------------------
// mode 0: g_h1 (fp16, perm rows). mode 1: fp32 out (scalar) + fp16 mirror g_h16.
__global__ void __launch_bounds__(256) k_red(const float* __restrict__ bias,
                                             float* __restrict__ outp,
                                             float invscale, int mode) {
    const int v = blockIdx.y, n0 = blockIdx.x * 128;
    const int tid = threadIdx.x;
    const int row = n0 + (tid >> 1);
    const int cb  = (tid & 1) * 64;
    const float dsc = g_dinv[v][row] * invscale;
    const size_t off = ((size_t)v*NN + row)*HH + cb;
    const size_t sstr = (size_t)VV*NN*HH;
    const float* p0 = &g_partial[0][0][0][0] + off;
    const int rp = perm_r(row);
    float* orow = (mode == 1) ? (outp + ((size_t)v*NN + row)*HH) : nullptr;
    #pragma unroll
    for (int j = 0; j < 64; j += 4) {
        float4 s = *reinterpret_cast<const float4*>(p0 + j);
        #pragma unroll
        for (int sl = 1; sl < KSPLIT; sl++) {
            float4 t = *reinterpret_cast<const float4*>(p0 + sl*sstr + j);
            s.x += t.x; s.y += t.y; s.z += t.z; s.w += t.w;
        }
        int col = cb + j;
        float r0 = fmaxf(fmaf(dsc, s.x, bias[v*HH + col    ]), 0.f);
        float r1 = fmaxf(fmaf(dsc, s.y, bias[v*HH + col + 1]), 0.f);
        float r2 = fmaxf(fmaf(dsc, s.z, bias[v*HH + col + 2]), 0.f);
        float r3 = fmaxf(fmaf(dsc, s.w, bias[v*HH + col + 3]), 0.f);
        if (mode == 0) {
            *reinterpret_cast<__half2*>(&g_h1[v][rp][col])     = __floats2half2_rn(r0, r1);
            *reinterpret_cast<__half2*>(&g_h1[v][rp][col + 2]) = __floats2half2_rn(r2, r3);
        } else {
            orow[col]     = r0;   // d_out region only 4B-aligned -> scalar stores
            orow[col + 1] = r1;
            orow[col + 2] = r2;
            orow[col + 3] = r3;
            *reinterpret_cast<__half2*>(&g_h16[v][row][col])     = __floats2half2_rn(r0, r1);
            *reinterpret_cast<__half2*>(&g_h16[v][row][col + 2]) = __floats2half2_rn(r2, r3);
        }
    }
}

// ---- K4b: B16 = dinvp * SCALE2 * (h1 @ W2), permuted row space ---------------------
#define MMA_SMEM (2*128*136*(int)sizeof(__half))
__global__ void __launch_bounds__(256) k_w2m(const float* __restrict__ W2) {
    extern __shared__ char smraw[];
    MRow* h1s = (MRow*)smraw;
    MRow* w2s = (MRow*)(smraw + 128*136*sizeof(__half));
    const int v = blockIdx.y, n0 = blockIdx.x * 128;
    const int tid = threadIdx.x, lane = tid & 31, warp = tid >> 5;
    const int wm = warp & 3, wn = warp >> 2;

    #pragma unroll
    for (int c = 0; c < 8; c++) {
        int e = tid + c*256;
        int r = e >> 4, u = e & 15;
        *reinterpret_cast<uint4*>(&h1s[r][u*8]) =
            *reinterpret_cast<const uint4*>(&g_h1[v][n0 + r][u*8]);
    }
    #pragma unroll
    for (int c = 0; c < 32; c++) {
        int e = tid + c*256;
        int h = e >> 6, p = e & 63;
        float2 f = *reinterpret_cast<const float2*>(&W2[((size_t)v*HH + h)*HH + p*2]);
        *reinterpret_cast<__half2*>(&w2s[h][p*2]) = __floats2half2_rn(f.x, f.y);
    }
    __syncthreads();

    Acc A; acc_zero(A);
    mma_chunk(A, h1s, w2s, lane, wm, wn);

    const int g = lane >> 2, cp2 = (lane & 3) * 2;
    #pragma unroll
    for (int mt = 0; mt < 2; mt++) {
        int r0 = n0 + wm*32 + mt*16 + g, r1 = r0 + 8;
        float d0 = g_dinvp[v][r0] * SCALE2;
        float d1 = g_dinvp[v][r1] * SCALE2;
        #pragma unroll
        for (int nt = 0; nt < 8; nt++) {
            int c0 = wn*64 + nt*8 + cp2;
            *reinterpret_cast<__half2*>(&g_B16[v][r0][c0]) =
                __floats2half2_rn(A.a[mt][nt][0]*d0, A.a[mt][nt][1]*d0);
            *reinterpret_cast<__half2*>(&g_B16[v][r1][c0]) =
                __floats2half2_rn(A.a[mt][nt][2]*d1, A.a[mt][nt][3]*d1);
        }
    }
}

// ---- K6: mean-pool partials (fp16 mirror source) -----------------------------------
__global__ void __launch_bounds__(128) k_part(int dummy) {
    const int p = blockIdx.x, v = blockIdx.y, h = threadIdx.x;
    float s = 0.f;
    const int span = NN / NPART;
    for (int n = p*span; n < (p+1)*span; n++)
        s += __half2float(g_h16[v][n][h]);
    g_part[v][p][h] = s;
    (void)dummy;
}

// ---- K7: summaries + attention softmax ---------------------------------------------
__global__ void __launch_bounds__(128) k_summ_attn(const float* __restrict__ Wa1,
                                                   const float* __restrict__ ba1,
                                                   const float* __restrict__ Wa2,
                                                   const float* __restrict__ ba2,
                                                   float* __restrict__ outattn) {
    __shared__ float summ[VV][HH];
    __shared__ float s1[ADIM];
    __shared__ float sc[VV];
    const int tid = threadIdx.x;
    #pragma unroll
    for (int v = 0; v < VV; v++) {
        float s = 0.f;
        #pragma unroll
        for (int p = 0; p < NPART; p++) s += g_part[v][p][tid];
        summ[v][tid] = s * (1.0f / (float)NN);
    }
    __syncthreads();
    for (int v = 0; v < VV; v++) {
        if (tid < ADIM) {
            float a = ba1[tid];
            for (int hh = 0; hh < HH; hh++) a = fmaf(summ[v][hh], Wa1[hh*ADIM + tid], a);
            s1[tid] = tanhf(a);
        }
        __syncthreads();
        if (tid == 0) {
            float sv = ba2[0];
            for (int j = 0; j < ADIM; j++) sv = fmaf(s1[j], Wa2[j], sv);
            sc[v] = sv;
        }
        __syncthreads();
    }
    if (tid == 0) {
        float m = fmaxf(sc[0], fmaxf(sc[1], sc[2]));
        float e0 = expf(sc[0]-m), e1 = expf(sc[1]-m), e2 = expf(sc[2]-m);
        float inv = 1.f / (e0 + e1 + e2);
        g_attn[0] = e0*inv; g_attn[1] = e1*inv; g_attn[2] = e2*inv;
        outattn[0] = e0*inv; outattn[1] = e1*inv; outattn[2] = e2*inv;
    }
}

// ---- K8: y1h = fp16(relu([h*attn] @ Wf1 + bf1)), vectorized fp16 A loads ----------
__global__ void __launch_bounds__(256) k_fuse1m(const float* __restrict__ Wf1,
                                                const float* __restrict__ bf1) {
    extern __shared__ char smraw[];
    MRow* h1s = (MRow*)smraw;
    MRow* w2s = (MRow*)(smraw + 128*136*sizeof(__half));
    const int n0 = blockIdx.x * 128;
    const int cb = blockIdx.y * 128;
    const int tid = threadIdx.x, lane = tid & 31, warp = tid >> 5;
    const int wm = warp & 3, wn = warp >> 2;

    Acc A; acc_zero(A);
    for (int v = 0; v < VV; v++) {
        float av = g_attn[v];
        #pragma unroll
        for (int c = 0; c < 8; c++) {
            int e = tid + c*256;
            int r = e >> 4, u = e & 15;
            uint4 pk = *reinterpret_cast<const uint4*>(&g_h16[v][n0 + r][u*8]);
            uint32_t* w = &pk.x;
            uint4 o;
            uint32_t* ow = &o.x;
            #pragma unroll
            for (int q = 0; q < 4; q++) {
                float2 f = __half22float2(*reinterpret_cast<__half2*>(&w[q]));
                __half2 hv = __floats2half2_rn(f.x * av, f.y * av);
                ow[q] = *reinterpret_cast<uint32_t*>(&hv);
            }
            *reinterpret_cast<uint4*>(&h1s[r][u*8]) = o;
        }
        #pragma unroll
        for (int c = 0; c < 32; c++) {
            int e = tid + c*256;
            int h = e >> 6, p = e & 63;
            float2 f = *reinterpret_cast<const float2*>(&Wf1[((size_t)(v*128 + h))*(2*HH) + cb + p*2]);
            *reinterpret_cast<__half2*>(&w2s[h][p*2]) = __floats2half2_rn(f.x, f.y);
        }
        __syncthreads();
        mma_chunk(A, h1s, w2s, lane, wm, wn);
        __syncthreads();
    }

    const int g = lane >> 2, cp2 = (lane & 3) * 2;
    #pragma unroll
    for (int mt = 0; mt < 2; mt++) {
        int r0 = n0 + wm*32 + mt*16 + g, r1 = r0 + 8;
        #pragma unroll
        for (int nt = 0; nt < 8; nt++) {
            int c0 = wn*64 + nt*8 + cp2;
            float b0 = bf1[cb + c0], b1 = bf1[cb + c0 + 1];
            *reinterpret_cast<__half2*>(&g_y1h[r0][cb + c0]) =
                __floats2half2_rn(fmaxf(A.a[mt][nt][0] + b0, 0.f), fmaxf(A.a[mt][nt][1] + b1, 0.f));
            *reinterpret_cast<__half2*>(&g_y1h[r1][cb + c0]) =
                __floats2half2_rn(fmaxf(A.a[mt][nt][2] + b0, 0.f), fmaxf(A.a[mt][nt][3] + b1, 0.f));
        }
    }
}

// ---- K9: fused = y1h @ Wf2 + bf2, tensor-core --------------------------------------
__global__ void __launch_bounds__(256) k_fuse2m(const float* __restrict__ Wf2,
                                                const float* __restrict__ bf2,
                                                float* __restrict__ outf) {
    extern __shared__ char smraw[];
    MRow* h1s = (MRow*)smraw;
    MRow* w2s = (MRow*)(smraw + 128*136*sizeof(__half));
    const int n0 = blockIdx.x * 128;
    const int tid = threadIdx.x, lane = tid & 31, warp = tid >> 5;
    const int wm = warp & 3, wn = warp >> 2;

    Acc A; acc_zero(A);
    for (int kk = 0; kk < 2; kk++) {
        #pragma unroll
        for (int c = 0; c < 8; c++) {
            int e = tid + c*256;
            int r = e >> 4, u = e & 15;
            *reinterpret_cast<uint4*>(&h1s[r][u*8]) =
                *reinterpret_cast<const uint4*>(&g_y1h[n0 + r][kk*128 + u*8]);
        }
        #pragma unroll
        for (int c = 0; c < 32; c++) {
            int e = tid + c*256;
            int h = e >> 6, p = e & 63;
            float2 f = *reinterpret_cast<const float2*>(&Wf2[((size_t)(kk*128 + h))*FOUT + p*2]);
            *reinterpret_cast<__half2*>(&w2s[h][p*2]) = __floats2half2_rn(f.x, f.y);
        }
        __syncthreads();
        mma_chunk(A, h1s, w2s, lane, wm, wn);
        __syncthreads();
    }

    const int g = lane >> 2, cp2 = (lane & 3) * 2;
    #pragma unroll
    for (int mt = 0; mt < 2; mt++) {
        int r0 = n0 + wm*32 + mt*16 + g, r1 = r0 + 8;
        #pragma unroll
        for (int nt = 0; nt < 8; nt++) {
            int c0 = wn*64 + nt*8 + cp2;
            float b0 = bf2[c0], b1 = bf2[c0 + 1];
            *reinterpret_cast<float2*>(&outf[(size_t)r0*FOUT + c0]) =
                make_float2(A.a[mt][nt][0] + b0, A.a[mt][nt][1] + b1);
            *reinterpret_cast<float2*>(&outf[(size_t)r1*FOUT + c0]) =
                make_float2(A.a[mt][nt][2] + b0, A.a[mt][nt][3] + b1);
        }
    }
}

// ---- launch ------------------------------------------------------------------------
extern "C" void kernel_launch(void* const* d_in, const int* in_sizes, int n_in,
                              void* d_out, int out_size) {
    const int*   adj = (const int*)  d_in[0];
    const float* W1  = (const float*)d_in[1];
    const float* b1  = (const float*)d_in[2];
    const float* W2  = (const float*)d_in[3];
    const float* b2  = (const float*)d_in[4];
    const float* Wa1 = (const float*)d_in[5];
    const float* ba1 = (const float*)d_in[6];
    const float* Wa2 = (const float*)d_in[7];
    const float* ba2 = (const float*)d_in[8];
    const float* Wf1 = (const float*)d_in[9];
    const float* bf1 = (const float*)d_in[10];
    const float* Wf2 = (const float*)d_in[11];
    const float* bf2 = (const float*)d_in[12];

    float* out       = (float*)d_out;
    float* out_fused = out;                                   // (N, F_OUT) — base 16B aligned
    float* out_attn  = out + (size_t)NN * FOUT;               // (V,)
    float* out_h     = out + (size_t)NN * FOUT + VV;          // (V, N, H) — only 4B aligned

    static int configured = 0;
    if (!configured) {
        cudaFuncSetAttribute(k_gemm,   cudaFuncAttributeMaxDynamicSharedMemorySize, GEMM_SMEM);
        cudaFuncSetAttribute(k_w2m,    cudaFuncAttributeMaxDynamicSharedMemorySize, MMA_SMEM);
        cudaFuncSetAttribute(k_fuse1m, cudaFuncAttributeMaxDynamicSharedMemorySize, MMA_SMEM);
        cudaFuncSetAttribute(k_fuse2m, cudaFuncAttributeMaxDynamicSharedMemorySize, MMA_SMEM);
        configured = 1;
    }

    k_pack<<<dim3(NN, VV), 256>>>(adj, W1);
    k_gemm<<<dim3(NN/128, VV, KSPLIT), 256, GEMM_SMEM>>>(0);
    k_red<<<dim3(NN/128, VV), 256>>>(b1, nullptr, 1.0f/SCALE1, 0);
    k_w2m<<<dim3(NN/128, VV), 256, MMA_SMEM>>>(W2);
    k_gemm<<<dim3(NN/128, VV, KSPLIT), 256, GEMM_SMEM>>>(0);
    k_red<<<dim3(NN/128, VV), 256>>>(b2, out_h, 1.0f/SCALE2, 1);
    k_part<<<dim3(NPART, VV), 128>>>(0);
    k_summ_attn<<<1, 128>>>(Wa1, ba1, Wa2, ba2, out_attn);
    k_fuse1m<<<dim3(NN/128, 2), 256, MMA_SMEM>>>(Wf1, bf1);
    k_fuse2m<<<NN/128, 256, MMA_SMEM>>>(Wf2, bf2, out_fused);
}

// round 16
// speedup vs baseline: 1.3096x; 1.0442x over previous
#include <cuda_runtime.h>
#include <cuda_fp16.h>
#include <stdint.h>

#define VV 3
#define NN 8192
#define HH 128
#define ADIM 64
#define FOUT 128
#define WORDS 256
#define SCALE1 256.0f
#define SCALE2 1024.0f
#define KSPLIT 3
#define NPART 64

static __device__ uint32_t g_packed[VV][NN][WORDS];              // word 4c+k, bit l <-> col 128c+4l+k
static __device__ float    g_dinv[VV][NN];                       // natural order
static __device__ float    g_dinvp[VV][NN];                      // permuted order
static __device__ __align__(16) __half g_B16[VV][NN][HH];        // B operand, PERMUTED rows
static __device__ __align__(16) __half g_h1[VV][NN][HH];         // fp16 h1, PERMUTED rows
static __device__ __align__(16) __half g_h16[VV][NN][HH];        // fp16 mirror of h (natural rows)
static __device__ __align__(16) __half g_partial[KSPLIT][VV][NN][HH];  // fp16 split-K partials (18.9 MB)
static __device__ __align__(16) __half g_y1h[NN][2*HH];          // fusion hidden, fp16
static __device__ float    g_part[VV][NPART][HH];
static __device__ float    g_attn[VV];

__device__ __forceinline__ int perm_r(int m) {
    return ((m >> 7) << 7) | ((m & 3) << 5) | (((m >> 2) & 15) << 1) | ((m >> 6) & 1);
}

// ---- K1: pack bits (permuted word order) + degree + B16 = dinv*W1*SCALE1 ----------
__global__ void __launch_bounds__(256) k_pack(const int* __restrict__ adj,
                                              const float* __restrict__ W1) {
    const int row = blockIdx.x, v = blockIdx.y;
    const int tid = threadIdx.x, lane = tid & 31, warp = tid >> 5;
    const int4* __restrict__ arow =
        reinterpret_cast<const int4*>(adj + ((size_t)v*NN + row)*(size_t)NN);
    int cnt = 0;
    #pragma unroll
    for (int c = warp; c < 64; c += 8) {
        int4 x = __ldg(&arow[c*32 + lane]);
        int base = c*128 + lane*4;
        bool b0 = (x.x != 0) || (base + 0 == row);
        bool b1 = (x.y != 0) || (base + 1 == row);
        bool b2 = (x.z != 0) || (base + 2 == row);
        bool b3 = (x.w != 0) || (base + 3 == row);
        unsigned m0 = __ballot_sync(0xffffffffu, b0);
        unsigned m1 = __ballot_sync(0xffffffffu, b1);
        unsigned m2 = __ballot_sync(0xffffffffu, b2);
        unsigned m3 = __ballot_sync(0xffffffffu, b3);
        if (lane == 0)
            *reinterpret_cast<uint4*>(&g_packed[v][row][4*c]) = make_uint4(m0, m1, m2, m3);
        cnt += (int)b0 + (int)b1 + (int)b2 + (int)b3;
    }
    #pragma unroll
    for (int o = 16; o; o >>= 1) cnt += __shfl_xor_sync(0xffffffffu, cnt, o);
    __shared__ int sc[8];
    __shared__ float sdinv;
    if (lane == 0) sc[warp] = cnt;
    __syncthreads();
    if (tid == 0) {
        int d = 0;
        #pragma unroll
        for (int i = 0; i < 8; i++) d += sc[i];
        float di = rsqrtf((float)d);
        sdinv = di;
        g_dinv[v][row] = di;
        g_dinvp[v][perm_r(row)] = di;
    }
    __syncthreads();
    if (tid < HH) {
        int rp = perm_r(row);
        g_B16[v][rp][tid] = __float2half(W1[((size_t)v*NN + row)*HH + tid] * sdinv * SCALE1);
    }
}

// ---- mma helpers -------------------------------------------------------------------
__device__ __forceinline__ uint32_t smem_u32(const void* p) {
    return (uint32_t)__cvta_generic_to_shared(p);
}
__device__ __forceinline__ void ldsm_x4(uint32_t& r0, uint32_t& r1, uint32_t& r2, uint32_t& r3, uint32_t a) {
    asm volatile("ldmatrix.sync.aligned.m8n8.x4.shared.b16 {%0,%1,%2,%3}, [%4];"
                 : "=r"(r0), "=r"(r1), "=r"(r2), "=r"(r3) : "r"(a));
}
__device__ __forceinline__ void ldsm_x4_t(uint32_t& r0, uint32_t& r1, uint32_t& r2, uint32_t& r3, uint32_t a) {
    asm volatile("ldmatrix.sync.aligned.m8n8.x4.trans.shared.b16 {%0,%1,%2,%3}, [%4];"
                 : "=r"(r0), "=r"(r1), "=r"(r2), "=r"(r3) : "r"(a));
}
__device__ __forceinline__ void mma16816(float* c, const uint32_t* a, const uint32_t* b) {
    asm volatile("mma.sync.aligned.m16n8k16.row.col.f32.f16.f16.f32 "
                 "{%0,%1,%2,%3}, {%4,%5,%6,%7}, {%8,%9}, {%0,%1,%2,%3};"
                 : "+f"(c[0]), "+f"(c[1]), "+f"(c[2]), "+f"(c[3])
                 : "r"(a[0]), "r"(a[1]), "r"(a[2]), "r"(a[3]), "r"(b[0]), "r"(b[1]));
}
#define CP_ASYNC16(dst, src) \
    asm volatile("cp.async.cg.shared.global [%0], [%1], 16;" :: "r"(dst), "l"(src))
#define CP_COMMIT()   asm volatile("cp.async.commit_group;")
#define CP_WAIT(n)    asm volatile("cp.async.wait_group %0;" :: "n"(n))

// ---- shared mma-tile body (used by w2m/fuse kernels) -------------------------------
typedef __half MRow[136];
struct Acc { float a[2][8][4]; };
__device__ __forceinline__ void mma_chunk(Acc& A, const MRow* h1s, const MRow* w2s,
                                          int lane, int wm, int wn) {
    #pragma unroll
    for (int ks = 0; ks < 8; ks++) {
        const int k = ks * 16;
        uint32_t a[2][4];
        #pragma unroll
        for (int mt = 0; mt < 2; mt++) {
            const __half* p = &h1s[wm*32 + mt*16 + (lane & 7) + ((lane & 8) ? 8 : 0)]
                                  [k + ((lane & 16) ? 8 : 0)];
            ldsm_x4(a[mt][0], a[mt][1], a[mt][2], a[mt][3], smem_u32(p));
        }
        uint32_t b[8][2];
        #pragma unroll
        for (int nt2 = 0; nt2 < 4; nt2++) {
            int krow = k + (lane & 7) + ((lane & 8) ? 8 : 0);
            int ncol = wn*64 + nt2*16 + ((lane & 16) ? 8 : 0);
            uint32_t r0, r1, r2, r3;
            ldsm_x4_t(r0, r1, r2, r3, smem_u32(&w2s[krow][ncol]));
            b[nt2*2][0] = r0; b[nt2*2][1] = r1;
            b[nt2*2+1][0] = r2; b[nt2*2+1][1] = r3;
        }
        #pragma unroll
        for (int mt = 0; mt < 2; mt++)
            #pragma unroll
            for (int nt = 0; nt < 8; nt++)
                mma16816(A.a[mt][nt], a[mt], b[nt]);
    }
}
__device__ __forceinline__ void acc_zero(Acc& A) {
    #pragma unroll
    for (int a = 0; a < 2; a++)
        #pragma unroll
        for (int b = 0; b < 8; b++)
            #pragma unroll
            for (int c = 0; c < 4; c++) A.a[a][b][c] = 0.f;
}

// bit pair (q, q+16) of w -> fp16 {0,1} pair
__device__ __forceinline__ uint32_t bitcvt(uint32_t w, int q, __half2 c1024) {
    uint32_t t = ((w >> q) & 0x00010001u) | 0x64006400u;
    __half2 h = __hsub2(*(__half2*)&t, c1024);
    return *(uint32_t*)&h;
}

// ---- K2/K4: masked GEMM, split-K, K-chunk=128, 4x2 tiling, reg A frags,
// ----        3-stage B ring with ONE barrier per chunk; fp16 partials ---------------
#define GEMM_SMEM (3*128*136*(int)sizeof(__half))   // 3x B buffers = 104448
__global__ void __launch_bounds__(256, 2) k_gemm(int dummy) {
    extern __shared__ char smraw[];
    const int v  = blockIdx.y;
    const int n0 = blockIdx.x * 128;
    const int sl = blockIdx.z;
    const int c0 = (sl * 64) / KSPLIT;
    const int c1 = ((sl + 1) * 64) / KSPLIT;
    const int tid = threadIdx.x;
    const int lane = tid & 31, warp = tid >> 5;
    const int wm = warp & 3, wn = warp >> 2;
    const int g = lane >> 2, l3 = lane & 3;
    const __half2 c1024 = __half2half2(__ushort_as_half(0x6400));

    Acc A; acc_zero(A);
    const uint4* rowp[2][2];
    #pragma unroll
    for (int mt = 0; mt < 2; mt++)
        #pragma unroll
        for (int h = 0; h < 2; h++)
            rowp[mt][h] = reinterpret_cast<const uint4*>(
                g_packed[v][n0 + wm*32 + mt*16 + h*8 + g]);

    auto loadB = [&](int chunk, int buf) {
        MRow* Bs = (MRow*)(smraw + (size_t)buf*128*136*sizeof(__half));
        #pragma unroll
        for (int c = 0; c < 8; c++) {
            int ch = tid + c*256;
            int kr = ch >> 4, hc = (ch & 15) * 8;
            CP_ASYNC16(smem_u32(&Bs[kr][hc]), &g_B16[v][chunk*128 + kr][hc]);
        }
        CP_COMMIT();
    };

    loadB(c0, 0);
    for (int i = c0; i < c1; i++) {
        const int bi = (i - c0) % 3;
        MRow* Bcur = (MRow*)(smraw + (size_t)bi*128*136*sizeof(__half));
        uint32_t W[2][2][4];
        #pragma unroll
        for (int mt = 0; mt < 2; mt++)
            #pragma unroll
            for (int h = 0; h < 2; h++) {
                uint4 u = __ldg(&rowp[mt][h][i]);
                W[mt][h][0] = u.x; W[mt][h][1] = u.y; W[mt][h][2] = u.z; W[mt][h][3] = u.w;
            }
        if (i + 1 < c1) { loadB(i + 1, (i + 1 - c0) % 3); CP_WAIT(1); }
        else            { CP_WAIT(0); }
        __syncthreads();   // single barrier: publishes chunk i's B; also fences ring reuse

        #pragma unroll
        for (int ks = 0; ks < 8; ks++) {
            const int k = ks * 16;
            const int j  = ks >> 1;
            const int q0 = (ks & 1) * 8 + l3;
            uint32_t a[2][4];
            #pragma unroll
            for (int mt = 0; mt < 2; mt++) {
                a[mt][0] = bitcvt(W[mt][0][j], q0,     c1024);
                a[mt][1] = bitcvt(W[mt][1][j], q0,     c1024);
                a[mt][2] = bitcvt(W[mt][0][j], q0 + 4, c1024);
                a[mt][3] = bitcvt(W[mt][1][j], q0 + 4, c1024);
            }
            uint32_t b[8][2];
            #pragma unroll
            for (int nt2 = 0; nt2 < 4; nt2++) {
                int krow = k + (lane & 7) + ((lane & 8) ? 8 : 0);
                int ncol = wn*64 + nt2*16 + ((lane & 16) ? 8 : 0);
                uint32_t r0, r1, r2, r3;
                ldsm_x4_t(r0, r1, r2, r3, smem_u32(&Bcur[krow][ncol]));
                b[nt2*2][0] = r0; b[nt2*2][1] = r1;
                b[nt2*2+1][0] = r2; b[nt2*2+1][1] = r3;
            }
            #pragma unroll
            for (int mt = 0; mt < 2; mt++)
                #pragma unroll
                for (int nt = 0; nt < 8; nt++)
                    mma16816(A.a[mt][nt], a[mt], b[nt]);
        }
        // no trailing barrier: 3-stage ring; next iteration's barrier fences reuse
    }

    const int cp2 = l3 * 2;
    __half* pp = &g_partial[sl][v][0][0];
    #pragma unroll
    for (int mt = 0; mt < 2; mt++) {
        int nl0 = n0 + wm*32 + mt*16 + g, nl1 = nl0 + 8;
        #pragma unroll
        for (int nt = 0; nt < 8; nt++) {
            int cc = wn*64 + nt*8 + cp2;
            *reinterpret_cast<__half2*>(&pp[(size_t)nl0*HH + cc]) =
                __floats2half2_rn(A.a[mt][nt][0], A.a[mt][nt][1]);
            *reinterpret_cast<__half2*>(&pp[(size_t)nl1*HH + cc]) =
                __floats2half2_rn(A.a[mt][nt][2], A.a[mt][nt][3]);
        }
    }
    (void)dummy;
}

// ---- K3/K5: reduce fp16 split-K partials + epilogue --------------------------------
// mode 0: g_h1 (fp16, perm rows). mode 1: fp32 out (scalar) + fp16 mirror g_h16.
__global__ void __launch_bounds__(256) k_red(const float* __restrict__ bias,
                                             float* __restrict__ outp,
                                             float invscale, int mode) {
    const int v = blockIdx.y, n0 = blockIdx.x * 128;
    const int tid = threadIdx.x;
    const int row = n0 + (tid >> 1);
    const int cb  = (tid & 1) * 64;
    const float dsc = g_dinv[v][row] * invscale;
    const size_t off = ((size_t)v*NN + row)*HH + cb;
    const size_t sstr = (size_t)VV*NN*HH;
    const __half* p0 = &g_partial[0][0][0][0] + off;
    const int rp = perm_r(row);
    float* orow = (mode == 1) ? (outp + ((size_t)v*NN + row)*HH) : nullptr;
    #pragma unroll
    for (int j = 0; j < 64; j += 4) {
        float4 s = make_float4(0.f, 0.f, 0.f, 0.f);
        #pragma unroll
        for (int sl = 0; sl < KSPLIT; sl++) {
            __half2 a = *reinterpret_cast<const __half2*>(p0 + sl*sstr + j);
            __half2 b = *reinterpret_cast<const __half2*>(p0 + sl*sstr + j + 2);
            float2 fa = __half22float2(a), fb = __half22float2(b);
            s.x += fa.x; s.y += fa.y; s.z += fb.x; s.w += fb.y;
        }
        int col = cb + j;
        float r0 = fmaxf(fmaf(dsc, s.x, bias[v*HH + col    ]), 0.f);
        float r1 = fmaxf(fmaf(dsc, s.y, bias[v*HH + col + 1]), 0.f);
        float r2 = fmaxf(fmaf(dsc, s.z, bias[v*HH + col + 2]), 0.f);
        float r3 = fmaxf(fmaf(dsc, s.w, bias[v*HH + col + 3]), 0.f);
        if (mode == 0) {
            *reinterpret_cast<__half2*>(&g_h1[v][rp][col])     = __floats2half2_rn(r0, r1);
            *reinterpret_cast<__half2*>(&g_h1[v][rp][col + 2]) = __floats2half2_rn(r2, r3);
        } else {
            orow[col]     = r0;   // d_out region only 4B-aligned -> scalar stores
            orow[col + 1] = r1;
            orow[col + 2] = r2;
            orow[col + 3] = r3;
            *reinterpret_cast<__half2*>(&g_h16[v][row][col])     = __floats2half2_rn(r0, r1);
            *reinterpret_cast<__half2*>(&g_h16[v][row][col + 2]) = __floats2half2_rn(r2, r3);
        }
    }
}

// ---- K4b: B16 = dinvp * SCALE2 * (h1 @ W2), permuted row space ---------------------
#define MMA_SMEM (2*128*136*(int)sizeof(__half))
__global__ void __launch_bounds__(256, 2) k_w2m(const float* __restrict__ W2) {
    extern __shared__ char smraw[];
    MRow* h1s = (MRow*)smraw;
    MRow* w2s = (MRow*)(smraw + 128*136*sizeof(__half));
    const int v = blockIdx.y, n0 = blockIdx.x * 128;
    const int tid = threadIdx.x, lane = tid & 31, warp = tid >> 5;
    const int wm = warp & 3, wn = warp >> 2;

    #pragma unroll
    for (int c = 0; c < 8; c++) {
        int e = tid + c*256;
        int r = e >> 4, u = e & 15;
        *reinterpret_cast<uint4*>(&h1s[r][u*8]) =
            *reinterpret_cast<const uint4*>(&g_h1[v][n0 + r][u*8]);
    }
    #pragma unroll
    for (int c = 0; c < 32; c++) {
        int e = tid + c*256;
        int h = e >> 6, p = e & 63;
        float2 f = *reinterpret_cast<const float2*>(&W2[((size_t)v*HH + h)*HH + p*2]);
        *reinterpret_cast<__half2*>(&w2s[h][p*2]) = __floats2half2_rn(f.x, f.y);
    }
    __syncthreads();

    Acc A; acc_zero(A);
    mma_chunk(A, h1s, w2s, lane, wm, wn);

    const int g = lane >> 2, cp2 = (lane & 3) * 2;
    #pragma unroll
    for (int mt = 0; mt < 2; mt++) {
        int r0 = n0 + wm*32 + mt*16 + g, r1 = r0 + 8;
        float d0 = g_dinvp[v][r0] * SCALE2;
        float d1 = g_dinvp[v][r1] * SCALE2;
        #pragma unroll
        for (int nt = 0; nt < 8; nt++) {
            int c0 = wn*64 + nt*8 + cp2;
            *reinterpret_cast<__half2*>(&g_B16[v][r0][c0]) =
                __floats2half2_rn(A.a[mt][nt][0]*d0, A.a[mt][nt][1]*d0);
            *reinterpret_cast<__half2*>(&g_B16[v][r1][c0]) =
                __floats2half2_rn(A.a[mt][nt][2]*d1, A.a[mt][nt][3]*d1);
        }
    }
}

// ---- K6: mean-pool partials (fp16 mirror source) -----------------------------------
__global__ void __launch_bounds__(128) k_part(int dummy) {
    const int p = blockIdx.x, v = blockIdx.y, h = threadIdx.x;
    float s = 0.f;
    const int span = NN / NPART;
    for (int n = p*span; n < (p+1)*span; n++)
        s += __half2float(g_h16[v][n][h]);
    g_part[v][p][h] = s;
    (void)dummy;
}

// ---- K7: summaries + attention softmax ---------------------------------------------
__global__ void __launch_bounds__(128) k_summ_attn(const float* __restrict__ Wa1,
                                                   const float* __restrict__ ba1,
                                                   const float* __restrict__ Wa2,
                                                   const float* __restrict__ ba2,
                                                   float* __restrict__ outattn) {
    __shared__ float summ[VV][HH];
    __shared__ float s1[ADIM];
    __shared__ float sc[VV];
    const int tid = threadIdx.x;
    #pragma unroll
    for (int v = 0; v < VV; v++) {
        float s = 0.f;
        #pragma unroll
        for (int p = 0; p < NPART; p++) s += g_part[v][p][tid];
        summ[v][tid] = s * (1.0f / (float)NN);
    }
    __syncthreads();
    for (int v = 0; v < VV; v++) {
        if (tid < ADIM) {
            float a = ba1[tid];
            for (int hh = 0; hh < HH; hh++) a = fmaf(summ[v][hh], Wa1[hh*ADIM + tid], a);
            s1[tid] = tanhf(a);
        }
        __syncthreads();
        if (tid == 0) {
            float sv = ba2[0];
            for (int j = 0; j < ADIM; j++) sv = fmaf(s1[j], Wa2[j], sv);
            sc[v] = sv;
        }
        __syncthreads();
    }
    if (tid == 0) {
        float m = fmaxf(sc[0], fmaxf(sc[1], sc[2]));
        float e0 = expf(sc[0]-m), e1 = expf(sc[1]-m), e2 = expf(sc[2]-m);
        float inv = 1.f / (e0 + e1 + e2);
        g_attn[0] = e0*inv; g_attn[1] = e1*inv; g_attn[2] = e2*inv;
        outattn[0] = e0*inv; outattn[1] = e1*inv; outattn[2] = e2*inv;
    }
}

// ---- K8: y1h = fp16(relu([h*attn] @ Wf1 + bf1)), vectorized fp16 A loads ----------
__global__ void __launch_bounds__(256, 2) k_fuse1m(const float* __restrict__ Wf1,
                                                   const float* __restrict__ bf1) {
    extern __shared__ char smraw[];
    MRow* h1s = (MRow*)smraw;
    MRow* w2s = (MRow*)(smraw + 128*136*sizeof(__half));
    const int n0 = blockIdx.x * 128;
    const int cb = blockIdx.y * 128;
    const int tid = threadIdx.x, lane = tid & 31, warp = tid >> 5;
    const int wm = warp & 3, wn = warp >> 2;

    Acc A; acc_zero(A);
    for (int v = 0; v < VV; v++) {
        float av = g_attn[v];
        #pragma unroll
        for (int c = 0; c < 8; c++) {
            int e = tid + c*256;
            int r = e >> 4, u = e & 15;
            uint4 pk = *reinterpret_cast<const uint4*>(&g_h16[v][n0 + r][u*8]);
            uint32_t* w = &pk.x;
            uint4 o;
            uint32_t* ow = &o.x;
            #pragma unroll
            for (int q = 0; q < 4; q++) {
                float2 f = __half22float2(*reinterpret_cast<__half2*>(&w[q]));
                __half2 hv = __floats2half2_rn(f.x * av, f.y * av);
                ow[q] = *reinterpret_cast<uint32_t*>(&hv);
            }
            *reinterpret_cast<uint4*>(&h1s[r][u*8]) = o;
        }
        #pragma unroll
        for (int c = 0; c < 32; c++) {
            int e = tid + c*256;
            int h = e >> 6, p = e & 63;
            float2 f = *reinterpret_cast<const float2*>(&Wf1[((size_t)(v*128 + h))*(2*HH) + cb + p*2]);
            *reinterpret_cast<__half2*>(&w2s[h][p*2]) = __floats2half2_rn(f.x, f.y);
        }
        __syncthreads();
        mma_chunk(A, h1s, w2s, lane, wm, wn);
        __syncthreads();
    }

    const int g = lane >> 2, cp2 = (lane & 3) * 2;
    #pragma unroll
    for (int mt = 0; mt < 2; mt++) {
        int r0 = n0 + wm*32 + mt*16 + g, r1 = r0 + 8;
        #pragma unroll
        for (int nt = 0; nt < 8; nt++) {
            int c0 = wn*64 + nt*8 + cp2;
            float b0 = bf1[cb + c0], b1 = bf1[cb + c0 + 1];
            *reinterpret_cast<__half2*>(&g_y1h[r0][cb + c0]) =
                __floats2half2_rn(fmaxf(A.a[mt][nt][0] + b0, 0.f), fmaxf(A.a[mt][nt][1] + b1, 0.f));
            *reinterpret_cast<__half2*>(&g_y1h[r1][cb + c0]) =
                __floats2half2_rn(fmaxf(A.a[mt][nt][2] + b0, 0.f), fmaxf(A.a[mt][nt][3] + b1, 0.f));
        }
    }
}

// ---- K9: fused = y1h @ Wf2 + bf2, tensor-core --------------------------------------
__global__ void __launch_bounds__(256, 2) k_fuse2m(const float* __restrict__ Wf2,
                                                   const float* __restrict__ bf2,
                                                   float* __restrict__ outf) {
    extern __shared__ char smraw[];
    MRow* h1s = (MRow*)smraw;
    MRow* w2s = (MRow*)(smraw + 128*136*sizeof(__half));
    const int n0 = blockIdx.x * 128;
    const int tid = threadIdx.x, lane = tid & 31, warp = tid >> 5;
    const int wm = warp & 3, wn = warp >> 2;

    Acc A; acc_zero(A);
    for (int kk = 0; kk < 2; kk++) {
        #pragma unroll
        for (int c = 0; c < 8; c++) {
            int e = tid + c*256;
            int r = e >> 4, u = e & 15;
            *reinterpret_cast<uint4*>(&h1s[r][u*8]) =
                *reinterpret_cast<const uint4*>(&g_y1h[n0 + r][kk*128 + u*8]);
        }
        #pragma unroll
        for (int c = 0; c < 32; c++) {
            int e = tid + c*256;
            int h = e >> 6, p = e & 63;
            float2 f = *reinterpret_cast<const float2*>(&Wf2[((size_t)(kk*128 + h))*FOUT + p*2]);
            *reinterpret_cast<__half2*>(&w2s[h][p*2]) = __floats2half2_rn(f.x, f.y);
        }
        __syncthreads();
        mma_chunk(A, h1s, w2s, lane, wm, wn);
        __syncthreads();
    }

    const int g = lane >> 2, cp2 = (lane & 3) * 2;
    #pragma unroll
    for (int mt = 0; mt < 2; mt++) {
        int r0 = n0 + wm*32 + mt*16 + g, r1 = r0 + 8;
        #pragma unroll
        for (int nt = 0; nt < 8; nt++) {
            int c0 = wn*64 + nt*8 + cp2;
            float b0 = bf2[c0], b1 = bf2[c0 + 1];
            *reinterpret_cast<float2*>(&outf[(size_t)r0*FOUT + c0]) =
                make_float2(A.a[mt][nt][0] + b0, A.a[mt][nt][1] + b1);
            *reinterpret_cast<float2*>(&outf[(size_t)r1*FOUT + c0]) =
                make_float2(A.a[mt][nt][2] + b0, A.a[mt][nt][3] + b1);
        }
    }
}

// ---- launch ------------------------------------------------------------------------
extern "C" void kernel_launch(void* const* d_in, const int* in_sizes, int n_in,
                              void* d_out, int out_size) {
    const int*   adj = (const int*)  d_in[0];
    const float* W1  = (const float*)d_in[1];
    const float* b1  = (const float*)d_in[2];
    const float* W2  = (const float*)d_in[3];
    const float* b2  = (const float*)d_in[4];
    const float* Wa1 = (const float*)d_in[5];
    const float* ba1 = (const float*)d_in[6];
    const float* Wa2 = (const float*)d_in[7];
    const float* ba2 = (const float*)d_in[8];
    const float* Wf1 = (const float*)d_in[9];
    const float* bf1 = (const float*)d_in[10];
    const float* Wf2 = (const float*)d_in[11];
    const float* bf2 = (const float*)d_in[12];

    float* out       = (float*)d_out;
    float* out_fused = out;                                   // (N, F_OUT) — base 16B aligned
    float* out_attn  = out + (size_t)NN * FOUT;               // (V,)
    float* out_h     = out + (size_t)NN * FOUT + VV;          // (V, N, H) — only 4B aligned

    static int configured = 0;
    if (!configured) {
        cudaFuncSetAttribute(k_gemm,   cudaFuncAttributeMaxDynamicSharedMemorySize, GEMM_SMEM);
        cudaFuncSetAttribute(k_w2m,    cudaFuncAttributeMaxDynamicSharedMemorySize, MMA_SMEM);
        cudaFuncSetAttribute(k_fuse1m, cudaFuncAttributeMaxDynamicSharedMemorySize, MMA_SMEM);
        cudaFuncSetAttribute(k_fuse2m, cudaFuncAttributeMaxDynamicSharedMemorySize, MMA_SMEM);
        configured = 1;
    }

    k_pack<<<dim3(NN, VV), 256>>>(adj, W1);
    k_gemm<<<dim3(NN/128, VV, KSPLIT), 256, GEMM_SMEM>>>(0);
    k_red<<<dim3(NN/128, VV), 256>>>(b1, nullptr, 1.0f/SCALE1, 0);
    k_w2m<<<dim3(NN/128, VV), 256, MMA_SMEM>>>(W2);
    k_gemm<<<dim3(NN/128, VV, KSPLIT), 256, GEMM_SMEM>>>(0);
    k_red<<<dim3(NN/128, VV), 256>>>(b2, out_h, 1.0f/SCALE2, 1);
    k_part<<<dim3(NPART, VV), 128>>>(0);
    k_summ_attn<<<1, 128>>>(Wa1, ba1, Wa2, ba2, out_attn);
    k_fuse1m<<<dim3(NN/128, 2), 256, MMA_SMEM>>>(Wf1, bf1);
    k_fuse2m<<<NN/128, 256, MMA_SMEM>>>(Wf2, bf2, out_fused);
}

// round 17
// speedup vs baseline: 1.4236x; 1.0871x over previous
#include <cuda_runtime.h>
#include <cuda_fp16.h>
#include <stdint.h>

#define VV 3
#define NN 8192
#define HH 128
#define ADIM 64
#define FOUT 128
#define WORDS 256
#define SCALE1 256.0f
#define SCALE2 1024.0f
#define KSPLIT 3
#define NPART 64

static __device__ uint32_t g_packed[VV][NN][WORDS];              // word 4c+k, bit l <-> col 128c+4l+k
static __device__ float    g_dinv[VV][NN];                       // natural order
static __device__ float    g_dinvp[VV][NN];                      // permuted order
static __device__ __align__(16) __half g_B16[VV][NN][HH];        // B operand, PERMUTED rows
static __device__ __align__(16) __half g_h1[VV][NN][HH];         // fp16 h1, PERMUTED rows
static __device__ __align__(16) __half g_h16[VV][NN][HH];        // fp16 mirror of h (natural rows)
static __device__ __align__(16) __half g_partial[KSPLIT][VV][NN][HH];  // fp16 split-K partials (18.9 MB)
static __device__ __align__(16) __half g_y1h[NN][2*HH];          // fusion hidden, fp16
static __device__ float    g_part[VV][NPART][HH];
static __device__ float    g_attn[VV];

__device__ __forceinline__ int perm_r(int m) {
    return ((m >> 7) << 7) | ((m & 3) << 5) | (((m >> 2) & 15) << 1) | ((m >> 6) & 1);
}

// ---- K1: pack bits (permuted word order) + degree + B16 = dinv*W1*SCALE1 ----------
__global__ void __launch_bounds__(256) k_pack(const int* __restrict__ adj,
                                              const float* __restrict__ W1) {
    const int row = blockIdx.x, v = blockIdx.y;
    const int tid = threadIdx.x, lane = tid & 31, warp = tid >> 5;
    const int4* __restrict__ arow =
        reinterpret_cast<const int4*>(adj + ((size_t)v*NN + row)*(size_t)NN);
    int cnt = 0;
    #pragma unroll
    for (int c = warp; c < 64; c += 8) {
        int4 x = __ldg(&arow[c*32 + lane]);
        int base = c*128 + lane*4;
        bool b0 = (x.x != 0) || (base + 0 == row);
        bool b1 = (x.y != 0) || (base + 1 == row);
        bool b2 = (x.z != 0) || (base + 2 == row);
        bool b3 = (x.w != 0) || (base + 3 == row);
        unsigned m0 = __ballot_sync(0xffffffffu, b0);
        unsigned m1 = __ballot_sync(0xffffffffu, b1);
        unsigned m2 = __ballot_sync(0xffffffffu, b2);
        unsigned m3 = __ballot_sync(0xffffffffu, b3);
        if (lane == 0)
            *reinterpret_cast<uint4*>(&g_packed[v][row][4*c]) = make_uint4(m0, m1, m2, m3);
        cnt += (int)b0 + (int)b1 + (int)b2 + (int)b3;
    }
    #pragma unroll
    for (int o = 16; o; o >>= 1) cnt += __shfl_xor_sync(0xffffffffu, cnt, o);
    __shared__ int sc[8];
    __shared__ float sdinv;
    if (lane == 0) sc[warp] = cnt;
    __syncthreads();
    if (tid == 0) {
        int d = 0;
        #pragma unroll
        for (int i = 0; i < 8; i++) d += sc[i];
        float di = rsqrtf((float)d);
        sdinv = di;
        g_dinv[v][row] = di;
        g_dinvp[v][perm_r(row)] = di;
    }
    __syncthreads();
    if (tid < HH) {
        int rp = perm_r(row);
        g_B16[v][rp][tid] = __float2half(W1[((size_t)v*NN + row)*HH + tid] * sdinv * SCALE1);
    }
}

// ---- mma helpers -------------------------------------------------------------------
__device__ __forceinline__ uint32_t smem_u32(const void* p) {
    return (uint32_t)__cvta_generic_to_shared(p);
}
__device__ __forceinline__ void ldsm_x4(uint32_t& r0, uint32_t& r1, uint32_t& r2, uint32_t& r3, uint32_t a) {
    asm volatile("ldmatrix.sync.aligned.m8n8.x4.shared.b16 {%0,%1,%2,%3}, [%4];"
                 : "=r"(r0), "=r"(r1), "=r"(r2), "=r"(r3) : "r"(a));
}
__device__ __forceinline__ void ldsm_x4_t(uint32_t& r0, uint32_t& r1, uint32_t& r2, uint32_t& r3, uint32_t a) {
    asm volatile("ldmatrix.sync.aligned.m8n8.x4.trans.shared.b16 {%0,%1,%2,%3}, [%4];"
                 : "=r"(r0), "=r"(r1), "=r"(r2), "=r"(r3) : "r"(a));
}
__device__ __forceinline__ void mma16816(float* c, const uint32_t* a, const uint32_t* b) {
    asm volatile("mma.sync.aligned.m16n8k16.row.col.f32.f16.f16.f32 "
                 "{%0,%1,%2,%3}, {%4,%5,%6,%7}, {%8,%9}, {%0,%1,%2,%3};"
                 : "+f"(c[0]), "+f"(c[1]), "+f"(c[2]), "+f"(c[3])
                 : "r"(a[0]), "r"(a[1]), "r"(a[2]), "r"(a[3]), "r"(b[0]), "r"(b[1]));
}
#define CP_ASYNC16(dst, src) \
    asm volatile("cp.async.cg.shared.global [%0], [%1], 16;" :: "r"(dst), "l"(src))
#define CP_COMMIT()   asm volatile("cp.async.commit_group;")
#define CP_WAIT(n)    asm volatile("cp.async.wait_group %0;" :: "n"(n))

// ---- shared mma-tile body (used by w2m/fuse kernels) -------------------------------
typedef __half MRow[136];
struct Acc { float a[2][8][4]; };
__device__ __forceinline__ void mma_chunk(Acc& A, const MRow* h1s, const MRow* w2s,
                                          int lane, int wm, int wn) {
    #pragma unroll
    for (int ks = 0; ks < 8; ks++) {
        const int k = ks * 16;
        uint32_t a[2][4];
        #pragma unroll
        for (int mt = 0; mt < 2; mt++) {
            const __half* p = &h1s[wm*32 + mt*16 + (lane & 7) + ((lane & 8) ? 8 : 0)]
                                  [k + ((lane & 16) ? 8 : 0)];
            ldsm_x4(a[mt][0], a[mt][1], a[mt][2], a[mt][3], smem_u32(p));
        }
        uint32_t b[8][2];
        #pragma unroll
        for (int nt2 = 0; nt2 < 4; nt2++) {
            int krow = k + (lane & 7) + ((lane & 8) ? 8 : 0);
            int ncol = wn*64 + nt2*16 + ((lane & 16) ? 8 : 0);
            uint32_t r0, r1, r2, r3;
            ldsm_x4_t(r0, r1, r2, r3, smem_u32(&w2s[krow][ncol]));
            b[nt2*2][0] = r0; b[nt2*2][1] = r1;
            b[nt2*2+1][0] = r2; b[nt2*2+1][1] = r3;
        }
        #pragma unroll
        for (int mt = 0; mt < 2; mt++)
            #pragma unroll
            for (int nt = 0; nt < 8; nt++)
                mma16816(A.a[mt][nt], a[mt], b[nt]);
    }
}
__device__ __forceinline__ void acc_zero(Acc& A) {
    #pragma unroll
    for (int a = 0; a < 2; a++)
        #pragma unroll
        for (int b = 0; b < 8; b++)
            #pragma unroll
            for (int c = 0; c < 4; c++) A.a[a][b][c] = 0.f;
}

// bit pair (q, q+16) of w -> fp16 {0,1} pair
__device__ __forceinline__ uint32_t bitcvt(uint32_t w, int q, __half2 c1024) {
    uint32_t t = ((w >> q) & 0x00010001u) | 0x64006400u;
    __half2 h = __hsub2(*(__half2*)&t, c1024);
    return *(uint32_t*)&h;
}

// ---- K2/K4: masked GEMM, split-K, K-chunk=128, 4x2 tiling, reg A frags,
// ----        3-stage B ring with ONE barrier per chunk; fp16 partials ---------------
#define GEMM_SMEM (3*128*136*(int)sizeof(__half))   // 3x B buffers = 104448
__global__ void __launch_bounds__(256, 2) k_gemm(int dummy) {
    extern __shared__ char smraw[];
    const int v  = blockIdx.y;
    const int n0 = blockIdx.x * 128;
    const int sl = blockIdx.z;
    const int c0 = (sl * 64) / KSPLIT;
    const int c1 = ((sl + 1) * 64) / KSPLIT;
    const int tid = threadIdx.x;
    const int lane = tid & 31, warp = tid >> 5;
    const int wm = warp & 3, wn = warp >> 2;
    const int g = lane >> 2, l3 = lane & 3;
    const __half2 c1024 = __half2half2(__ushort_as_half(0x6400));

    Acc A; acc_zero(A);
    const uint4* rowp[2][2];
    #pragma unroll
    for (int mt = 0; mt < 2; mt++)
        #pragma unroll
        for (int h = 0; h < 2; h++)
            rowp[mt][h] = reinterpret_cast<const uint4*>(
                g_packed[v][n0 + wm*32 + mt*16 + h*8 + g]);

    auto loadB = [&](int chunk, int buf) {
        MRow* Bs = (MRow*)(smraw + (size_t)buf*128*136*sizeof(__half));
        #pragma unroll
        for (int c = 0; c < 8; c++) {
            int ch = tid + c*256;
            int kr = ch >> 4, hc = (ch & 15) * 8;
            CP_ASYNC16(smem_u32(&Bs[kr][hc]), &g_B16[v][chunk*128 + kr][hc]);
        }
        CP_COMMIT();
    };

    loadB(c0, 0);
    for (int i = c0; i < c1; i++) {
        const int bi = (i - c0) % 3;
        MRow* Bcur = (MRow*)(smraw + (size_t)bi*128*136*sizeof(__half));
        uint32_t W[2][2][4];
        #pragma unroll
        for (int mt = 0; mt < 2; mt++)
            #pragma unroll
            for (int h = 0; h < 2; h++) {
                uint4 u = __ldg(&rowp[mt][h][i]);
                W[mt][h][0] = u.x; W[mt][h][1] = u.y; W[mt][h][2] = u.z; W[mt][h][3] = u.w;
            }
        if (i + 1 < c1) { loadB(i + 1, (i + 1 - c0) % 3); CP_WAIT(1); }
        else            { CP_WAIT(0); }
        __syncthreads();   // single barrier: publishes chunk i's B; also fences ring reuse

        #pragma unroll
        for (int ks = 0; ks < 8; ks++) {
            const int k = ks * 16;
            const int j  = ks >> 1;
            const int q0 = (ks & 1) * 8 + l3;
            uint32_t a[2][4];
            #pragma unroll
            for (int mt = 0; mt < 2; mt++) {
                a[mt][0] = bitcvt(W[mt][0][j], q0,     c1024);
                a[mt][1] = bitcvt(W[mt][1][j], q0,     c1024);
                a[mt][2] = bitcvt(W[mt][0][j], q0 + 4, c1024);
                a[mt][3] = bitcvt(W[mt][1][j], q0 + 4, c1024);
            }
            uint32_t b[8][2];
            #pragma unroll
            for (int nt2 = 0; nt2 < 4; nt2++) {
                int krow = k + (lane & 7) + ((lane & 8) ? 8 : 0);
                int ncol = wn*64 + nt2*16 + ((lane & 16) ? 8 : 0);
                uint32_t r0, r1, r2, r3;
                ldsm_x4_t(r0, r1, r2, r3, smem_u32(&Bcur[krow][ncol]));
                b[nt2*2][0] = r0; b[nt2*2][1] = r1;
                b[nt2*2+1][0] = r2; b[nt2*2+1][1] = r3;
            }
            #pragma unroll
            for (int mt = 0; mt < 2; mt++)
                #pragma unroll
                for (int nt = 0; nt < 8; nt++)
                    mma16816(A.a[mt][nt], a[mt], b[nt]);
        }
        // no trailing barrier: 3-stage ring; next iteration's barrier fences reuse
    }

    const int cp2 = l3 * 2;
    __half* pp = &g_partial[sl][v][0][0];
    #pragma unroll
    for (int mt = 0; mt < 2; mt++) {
        int nl0 = n0 + wm*32 + mt*16 + g, nl1 = nl0 + 8;
        #pragma unroll
        for (int nt = 0; nt < 8; nt++) {
            int cc = wn*64 + nt*8 + cp2;
            *reinterpret_cast<__half2*>(&pp[(size_t)nl0*HH + cc]) =
                __floats2half2_rn(A.a[mt][nt][0], A.a[mt][nt][1]);
            *reinterpret_cast<__half2*>(&pp[(size_t)nl1*HH + cc]) =
                __floats2half2_rn(A.a[mt][nt][2], A.a[mt][nt][3]);
        }
    }
    (void)dummy;
}

// ---- K3/K5: reduce fp16 split-K partials + epilogue, warp-per-row (coalesced) ------
// mode 0: g_h1 (fp16, perm rows). mode 1: fp32 out (scalar, coalesced) + g_h16 mirror.
__global__ void __launch_bounds__(256) k_red(const float* __restrict__ bias,
                                             float* __restrict__ outp,
                                             float invscale, int mode) {
    const int v = blockIdx.y, n0 = blockIdx.x * 128;
    const int tid = threadIdx.x;
    const int warp = tid >> 5, lane = tid & 31;
    const int col = lane * 4;
    const size_t sstr = (size_t)VV*NN*HH;
    const float b0c = bias[v*HH + col],     b1c = bias[v*HH + col + 1];
    const float b2c = bias[v*HH + col + 2], b3c = bias[v*HH + col + 3];
    #pragma unroll
    for (int it = 0; it < 16; it++) {
        const int row = n0 + it*8 + warp;
        const float dsc = g_dinv[v][row] * invscale;
        const __half* p0 = &g_partial[0][0][0][0] + ((size_t)v*NN + row)*HH + col;
        float4 s = make_float4(0.f, 0.f, 0.f, 0.f);
        #pragma unroll
        for (int sl = 0; sl < KSPLIT; sl++) {
            uint2 u = *reinterpret_cast<const uint2*>(p0 + sl*sstr);
            float2 fa = __half22float2(*reinterpret_cast<__half2*>(&u.x));
            float2 fb = __half22float2(*reinterpret_cast<__half2*>(&u.y));
            s.x += fa.x; s.y += fa.y; s.z += fb.x; s.w += fb.y;
        }
        float r0 = fmaxf(fmaf(dsc, s.x, b0c), 0.f);
        float r1 = fmaxf(fmaf(dsc, s.y, b1c), 0.f);
        float r2 = fmaxf(fmaf(dsc, s.z, b2c), 0.f);
        float r3 = fmaxf(fmaf(dsc, s.w, b3c), 0.f);
        if (mode == 0) {
            const int rp = perm_r(row);
            *reinterpret_cast<__half2*>(&g_h1[v][rp][col])     = __floats2half2_rn(r0, r1);
            *reinterpret_cast<__half2*>(&g_h1[v][rp][col + 2]) = __floats2half2_rn(r2, r3);
        } else {
            float* orow = outp + ((size_t)v*NN + row)*HH;
            orow[col]     = r0;   // d_out region only 4B-aligned; warp-contiguous stores
            orow[col + 1] = r1;
            orow[col + 2] = r2;
            orow[col + 3] = r3;
            *reinterpret_cast<__half2*>(&g_h16[v][row][col])     = __floats2half2_rn(r0, r1);
            *reinterpret_cast<__half2*>(&g_h16[v][row][col + 2]) = __floats2half2_rn(r2, r3);
        }
    }
}

// ---- K4b: B16 = dinvp * SCALE2 * (h1 @ W2), permuted row space ---------------------
#define MMA_SMEM (2*128*136*(int)sizeof(__half))
__global__ void __launch_bounds__(256, 2) k_w2m(const float* __restrict__ W2) {
    extern __shared__ char smraw[];
    MRow* h1s = (MRow*)smraw;
    MRow* w2s = (MRow*)(smraw + 128*136*sizeof(__half));
    const int v = blockIdx.y, n0 = blockIdx.x * 128;
    const int tid = threadIdx.x, lane = tid & 31, warp = tid >> 5;
    const int wm = warp & 3, wn = warp >> 2;

    #pragma unroll
    for (int c = 0; c < 8; c++) {
        int e = tid + c*256;
        int r = e >> 4, u = e & 15;
        *reinterpret_cast<uint4*>(&h1s[r][u*8]) =
            *reinterpret_cast<const uint4*>(&g_h1[v][n0 + r][u*8]);
    }
    #pragma unroll
    for (int c = 0; c < 32; c++) {
        int e = tid + c*256;
        int h = e >> 6, p = e & 63;
        float2 f = *reinterpret_cast<const float2*>(&W2[((size_t)v*HH + h)*HH + p*2]);
        *reinterpret_cast<__half2*>(&w2s[h][p*2]) = __floats2half2_rn(f.x, f.y);
    }
    __syncthreads();

    Acc A; acc_zero(A);
    mma_chunk(A, h1s, w2s, lane, wm, wn);

    const int g = lane >> 2, cp2 = (lane & 3) * 2;
    #pragma unroll
    for (int mt = 0; mt < 2; mt++) {
        int r0 = n0 + wm*32 + mt*16 + g, r1 = r0 + 8;
        float d0 = g_dinvp[v][r0] * SCALE2;
        float d1 = g_dinvp[v][r1] * SCALE2;
        #pragma unroll
        for (int nt = 0; nt < 8; nt++) {
            int c0 = wn*64 + nt*8 + cp2;
            *reinterpret_cast<__half2*>(&g_B16[v][r0][c0]) =
                __floats2half2_rn(A.a[mt][nt][0]*d0, A.a[mt][nt][1]*d0);
            *reinterpret_cast<__half2*>(&g_B16[v][r1][c0]) =
                __floats2half2_rn(A.a[mt][nt][2]*d1, A.a[mt][nt][3]*d1);
        }
    }
}

// ---- K6: mean-pool partials (fp16 mirror source) -----------------------------------
__global__ void __launch_bounds__(128) k_part(int dummy) {
    const int p = blockIdx.x, v = blockIdx.y, h = threadIdx.x;
    float s = 0.f;
    const int span = NN / NPART;
    for (int n = p*span; n < (p+1)*span; n++)
        s += __half2float(g_h16[v][n][h]);
    g_part[v][p][h] = s;
    (void)dummy;
}

// ---- K7: summaries + attention softmax ---------------------------------------------
__global__ void __launch_bounds__(128) k_summ_attn(const float* __restrict__ Wa1,
                                                   const float* __restrict__ ba1,
                                                   const float* __restrict__ Wa2,
                                                   const float* __restrict__ ba2,
                                                   float* __restrict__ outattn) {
    __shared__ float summ[VV][HH];
    __shared__ float s1[ADIM];
    __shared__ float sc[VV];
    const int tid = threadIdx.x;
    #pragma unroll
    for (int v = 0; v < VV; v++) {
        float s = 0.f;
        #pragma unroll
        for (int p = 0; p < NPART; p++) s += g_part[v][p][tid];
        summ[v][tid] = s * (1.0f / (float)NN);
    }
    __syncthreads();
    for (int v = 0; v < VV; v++) {
        if (tid < ADIM) {
            float a = ba1[tid];
            for (int hh = 0; hh < HH; hh++) a = fmaf(summ[v][hh], Wa1[hh*ADIM + tid], a);
            s1[tid] = tanhf(a);
        }
        __syncthreads();
        if (tid == 0) {
            float sv = ba2[0];
            for (int j = 0; j < ADIM; j++) sv = fmaf(s1[j], Wa2[j], sv);
            sc[v] = sv;
        }
        __syncthreads();
    }
    if (tid == 0) {
        float m = fmaxf(sc[0], fmaxf(sc[1], sc[2]));
        float e0 = expf(sc[0]-m), e1 = expf(sc[1]-m), e2 = expf(sc[2]-m);
        float inv = 1.f / (e0 + e1 + e2);
        g_attn[0] = e0*inv; g_attn[1] = e1*inv; g_attn[2] = e2*inv;
        outattn[0] = e0*inv; outattn[1] = e1*inv; outattn[2] = e2*inv;
    }
}

// ---- K8: y1h = fp16(relu([h*attn] @ Wf1 + bf1)), vectorized fp16 A loads ----------
__global__ void __launch_bounds__(256, 2) k_fuse1m(const float* __restrict__ Wf1,
                                                   const float* __restrict__ bf1) {
    extern __shared__ char smraw[];
    MRow* h1s = (MRow*)smraw;
    MRow* w2s = (MRow*)(smraw + 128*136*sizeof(__half));
    const int n0 = blockIdx.x * 128;
    const int cb = blockIdx.y * 128;
    const int tid = threadIdx.x, lane = tid & 31, warp = tid >> 5;
    const int wm = warp & 3, wn = warp >> 2;

    Acc A; acc_zero(A);
    for (int v = 0; v < VV; v++) {
        float av = g_attn[v];
        #pragma unroll
        for (int c = 0; c < 8; c++) {
            int e = tid + c*256;
            int r = e >> 4, u = e & 15;
            uint4 pk = *reinterpret_cast<const uint4*>(&g_h16[v][n0 + r][u*8]);
            uint32_t* w = &pk.x;
            uint4 o;
            uint32_t* ow = &o.x;
            #pragma unroll
            for (int q = 0; q < 4; q++) {
                float2 f = __half22float2(*reinterpret_cast<__half2*>(&w[q]));
                __half2 hv = __floats2half2_rn(f.x * av, f.y * av);
                ow[q] = *reinterpret_cast<uint32_t*>(&hv);
            }
            *reinterpret_cast<uint4*>(&h1s[r][u*8]) = o;
        }
        #pragma unroll
        for (int c = 0; c < 32; c++) {
            int e = tid + c*256;
            int h = e >> 6, p = e & 63;
            float2 f = *reinterpret_cast<const float2*>(&Wf1[((size_t)(v*128 + h))*(2*HH) + cb + p*2]);
            *reinterpret_cast<__half2*>(&w2s[h][p*2]) = __floats2half2_rn(f.x, f.y);
        }
        __syncthreads();
        mma_chunk(A, h1s, w2s, lane, wm, wn);
        __syncthreads();
    }

    const int g = lane >> 2, cp2 = (lane & 3) * 2;
    #pragma unroll
    for (int mt = 0; mt < 2; mt++) {
        int r0 = n0 + wm*32 + mt*16 + g, r1 = r0 + 8;
        #pragma unroll
        for (int nt = 0; nt < 8; nt++) {
            int c0 = wn*64 + nt*8 + cp2;
            float b0 = bf1[cb + c0], b1 = bf1[cb + c0 + 1];
            *reinterpret_cast<__half2*>(&g_y1h[r0][cb + c0]) =
                __floats2half2_rn(fmaxf(A.a[mt][nt][0] + b0, 0.f), fmaxf(A.a[mt][nt][1] + b1, 0.f));
            *reinterpret_cast<__half2*>(&g_y1h[r1][cb + c0]) =
                __floats2half2_rn(fmaxf(A.a[mt][nt][2] + b0, 0.f), fmaxf(A.a[mt][nt][3] + b1, 0.f));
        }
    }
}

// ---- K9: fused = y1h @ Wf2 + bf2, tensor-core --------------------------------------
__global__ void __launch_bounds__(256, 2) k_fuse2m(const float* __restrict__ Wf2,
                                                   const float* __restrict__ bf2,
                                                   float* __restrict__ outf) {
    extern __shared__ char smraw[];
    MRow* h1s = (MRow*)smraw;
    MRow* w2s = (MRow*)(smraw + 128*136*sizeof(__half));
    const int n0 = blockIdx.x * 128;
    const int tid = threadIdx.x, lane = tid & 31, warp = tid >> 5;
    const int wm = warp & 3, wn = warp >> 2;

    Acc A; acc_zero(A);
    for (int kk = 0; kk < 2; kk++) {
        #pragma unroll
        for (int c = 0; c < 8; c++) {
            int e = tid + c*256;
            int r = e >> 4, u = e & 15;
            *reinterpret_cast<uint4*>(&h1s[r][u*8]) =
                *reinterpret_cast<const uint4*>(&g_y1h[n0 + r][kk*128 + u*8]);
        }
        #pragma unroll
        for (int c = 0; c < 32; c++) {
            int e = tid + c*256;
            int h = e >> 6, p = e & 63;
            float2 f = *reinterpret_cast<const float2*>(&Wf2[((size_t)(kk*128 + h))*FOUT + p*2]);
            *reinterpret_cast<__half2*>(&w2s[h][p*2]) = __floats2half2_rn(f.x, f.y);
        }
        __syncthreads();
        mma_chunk(A, h1s, w2s, lane, wm, wn);
        __syncthreads();
    }

    const int g = lane >> 2, cp2 = (lane & 3) * 2;
    #pragma unroll
    for (int mt = 0; mt < 2; mt++) {
        int r0 = n0 + wm*32 + mt*16 + g, r1 = r0 + 8;
        #pragma unroll
        for (int nt = 0; nt < 8; nt++) {
            int c0 = wn*64 + nt*8 + cp2;
            float b0 = bf2[c0], b1 = bf2[c0 + 1];
            *reinterpret_cast<float2*>(&outf[(size_t)r0*FOUT + c0]) =
                make_float2(A.a[mt][nt][0] + b0, A.a[mt][nt][1] + b1);
            *reinterpret_cast<float2*>(&outf[(size_t)r1*FOUT + c0]) =
                make_float2(A.a[mt][nt][2] + b0, A.a[mt][nt][3] + b1);
        }
    }
}

// ---- launch ------------------------------------------------------------------------
extern "C" void kernel_launch(void* const* d_in, const int* in_sizes, int n_in,
                              void* d_out, int out_size) {
    const int*   adj = (const int*)  d_in[0];
    const float* W1  = (const float*)d_in[1];
    const float* b1  = (const float*)d_in[2];
    const float* W2  = (const float*)d_in[3];
    const float* b2  = (const float*)d_in[4];
    const float* Wa1 = (const float*)d_in[5];
    const float* ba1 = (const float*)d_in[6];
    const float* Wa2 = (const float*)d_in[7];
    const float* ba2 = (const float*)d_in[8];
    const float* Wf1 = (const float*)d_in[9];
    const float* bf1 = (const float*)d_in[10];
    const float* Wf2 = (const float*)d_in[11];
    const float* bf2 = (const float*)d_in[12];

    float* out       = (float*)d_out;
    float* out_fused = out;                                   // (N, F_OUT) — base 16B aligned
    float* out_attn  = out + (size_t)NN * FOUT;               // (V,)
    float* out_h     = out + (size_t)NN * FOUT + VV;          // (V, N, H) — only 4B aligned

    static int configured = 0;
    if (!configured) {
        cudaFuncSetAttribute(k_gemm,   cudaFuncAttributeMaxDynamicSharedMemorySize, GEMM_SMEM);
        cudaFuncSetAttribute(k_w2m,    cudaFuncAttributeMaxDynamicSharedMemorySize, MMA_SMEM);
        cudaFuncSetAttribute(k_fuse1m, cudaFuncAttributeMaxDynamicSharedMemorySize, MMA_SMEM);
        cudaFuncSetAttribute(k_fuse2m, cudaFuncAttributeMaxDynamicSharedMemorySize, MMA_SMEM);
        configured = 1;
    }

    k_pack<<<dim3(NN, VV), 256>>>(adj, W1);
    k_gemm<<<dim3(NN/128, VV, KSPLIT), 256, GEMM_SMEM>>>(0);
    k_red<<<dim3(NN/128, VV), 256>>>(b1, nullptr, 1.0f/SCALE1, 0);
    k_w2m<<<dim3(NN/128, VV), 256, MMA_SMEM>>>(W2);
    k_gemm<<<dim3(NN/128, VV, KSPLIT), 256, GEMM_SMEM>>>(0);
    k_red<<<dim3(NN/128, VV), 256>>>(b2, out_h, 1.0f/SCALE2, 1);
    k_part<<<dim3(NPART, VV), 128>>>(0);
    k_summ_attn<<<1, 128>>>(Wa1, ba1, Wa2, ba2, out_attn);
    k_fuse1m<<<dim3(NN/128, 2), 256, MMA_SMEM>>>(Wf1, bf1);
    k_fuse2m<<<NN/128, 256, MMA_SMEM>>>(Wf2, bf2, out_fused);
}